// round 4
// baseline (speedup 1.0000x reference)
#include <cuda_runtime.h>
#include <math.h>

#define D       128
#define NN      50000
#define NE      600000
#define EPS_BN  1e-5f
#define EPS_ETA 1e-6f
#define NBLK    148
#define NTHR    256

// ---------------- device-global scratch (no allocations allowed) -------------
__device__ float g_b1h[NN * D];
__device__ float g_b2h[NN * D];
__device__ float g_a1h[NN * D];
__device__ float g_v[NN * D];
__device__ float g_c1p[NN * D];
__device__ float g_c2p[NN * D];
__device__ float g_sum_sigma[NN * D];
__device__ float g_agg_h[NN * D];
__device__ float g_agg_p[NN * D];
__device__ float g_stats[4 * D];       // e_sum, e_sq, h_sum, h_sq
__device__ int            g_bar_count = 0;
__device__ volatile int   g_bar_gen   = 0;

__device__ __forceinline__ float sigf(float x) { return 1.0f / (1.0f + __expf(-x)); }

// ---------------- software grid barrier (all NBLK blocks co-resident) --------
__device__ __forceinline__ void grid_barrier()
{
    __syncthreads();
    if (threadIdx.x == 0) {
        int gen = g_bar_gen;
        __threadfence();
        if (atomicAdd(&g_bar_count, 1) == NBLK - 1) {
            g_bar_count = 0;
            __threadfence();
            g_bar_gen = gen + 1;
        } else {
            while (g_bar_gen == gen) { __nanosleep(64); }
        }
        __threadfence();
    }
    __syncthreads();
}

// ---------------- FMA micro-tile ----------------------------------------------
// ws: [16][128] k-major chunk; xs: [64][128]; 4 k-steps, 8 rows, 4 cols.
__device__ __forceinline__ void mm_step(
    const float* ws, const float* xs,
    int kk, int kbase, int r0, int c0, float4* acc)
{
    float4 w0 = *(const float4*)(ws + (kk + 0) * D + c0);
    float4 w1 = *(const float4*)(ws + (kk + 1) * D + c0);
    float4 w2 = *(const float4*)(ws + (kk + 2) * D + c0);
    float4 w3 = *(const float4*)(ws + (kk + 3) * D + c0);
#pragma unroll
    for (int j = 0; j < 8; j++) {
        float4 xv = *(const float4*)(xs + (r0 + j) * D + kbase + kk);
        acc[j].x = fmaf(xv.x, w0.x, acc[j].x);
        acc[j].y = fmaf(xv.x, w0.y, acc[j].y);
        acc[j].z = fmaf(xv.x, w0.z, acc[j].z);
        acc[j].w = fmaf(xv.x, w0.w, acc[j].w);
        acc[j].x = fmaf(xv.y, w1.x, acc[j].x);
        acc[j].y = fmaf(xv.y, w1.y, acc[j].y);
        acc[j].z = fmaf(xv.y, w1.z, acc[j].z);
        acc[j].w = fmaf(xv.y, w1.w, acc[j].w);
        acc[j].x = fmaf(xv.z, w2.x, acc[j].x);
        acc[j].y = fmaf(xv.z, w2.y, acc[j].y);
        acc[j].z = fmaf(xv.z, w2.z, acc[j].z);
        acc[j].w = fmaf(xv.z, w2.w, acc[j].w);
        acc[j].x = fmaf(xv.w, w3.x, acc[j].x);
        acc[j].y = fmaf(xv.w, w3.y, acc[j].y);
        acc[j].z = fmaf(xv.w, w3.z, acc[j].z);
        acc[j].w = fmaf(xv.w, w3.w, acc[j].w);
    }
}

// =============================================================================
// The single fused persistent kernel. grid = 148 x 256.
// =============================================================================
__global__ void __launch_bounds__(NTHR) fused_gcn(
    const float* __restrict__ h, const float* __restrict__ e, const float* __restrict__ p,
    const int* __restrict__ src, const int* __restrict__ dst,
    const float* __restrict__ A1w, const float* __restrict__ A1b,
    const float* __restrict__ A2w, const float* __restrict__ A2b,
    const float* __restrict__ B1w, const float* __restrict__ B1b,
    const float* __restrict__ B2w, const float* __restrict__ B2b,
    const float* __restrict__ B3w, const float* __restrict__ B3b,
    const float* __restrict__ C1w, const float* __restrict__ C1b,
    const float* __restrict__ C2w, const float* __restrict__ C2b,
    const float* __restrict__ bn_h_g, const float* __restrict__ bn_h_b,
    const float* __restrict__ bn_e_g, const float* __restrict__ bn_e_b,
    float* __restrict__ h_out, float* __restrict__ ehat, float* __restrict__ p_out)
{
    __shared__ __align__(16) float xs[64 * D];   // 32 KB
    __shared__ __align__(16) float ws[16 * D];   // 8 KB (also BN ss in final phase)
    __shared__ float sA[D];
    __shared__ float sB[D];

    const int tid  = threadIdx.x;
    const int lane = tid & 31;
    const int warp = tid >> 5;
    const int bid  = blockIdx.x;
    const int c0   = lane * 4;
    const int r0   = warp * 8;
    const int gtid = bid * NTHR + tid;
    const int gstr = NBLK * NTHR;       // 37888

    // ---------------- P0: zero accumulators ----------------
    {
        float4 z = make_float4(0.f, 0.f, 0.f, 0.f);
        for (int i = gtid; i < NN * D / 4; i += gstr) {
            ((float4*)g_sum_sigma)[i] = z;
            ((float4*)g_agg_h)[i] = z;
            ((float4*)g_agg_p)[i] = z;
        }
        if (gtid < 4 * D) g_stats[gtid] = 0.f;
    }
    grid_barrier();

    // ---------------- P1: node GEMMs (6 x 782 tile jobs) ----------------
    {
        const int NTILE = (NN + 63) / 64;    // 782
        for (int job = bid; job < 6 * NTILE; job += NBLK) {
            int jid  = job / NTILE;
            int tile = job - jid * NTILE;
            int row0 = tile * 64;
            const float *X1 = h, *X2 = nullptr, *W = B1w, *bias = B1b;
            float* outp = g_b1h;
            int ldw = D, nhalf = 1;
            if      (jid == 1) { X1 = h; W = B2w; bias = B2b; outp = g_b2h; }
            else if (jid == 2) { X1 = h; W = A1w; bias = A1b; outp = g_a1h; }
            else if (jid == 3) { X1 = p; W = C1w; bias = C1b; outp = g_c1p; }
            else if (jid == 4) { X1 = p; W = C2w; bias = C2b; outp = g_c2p; }
            else if (jid == 5) { X1 = h; X2 = p; W = A2w; bias = A2b; outp = g_v; ldw = 2 * D; nhalf = 2; }

            float4 acc[8];
#pragma unroll
            for (int j = 0; j < 8; j++) acc[j] = make_float4(0.f, 0.f, 0.f, 0.f);

            for (int half = 0; half < nhalf; half++) {
                const float* Xc = (half == 0) ? X1 : X2;
                const float* Wc = W + half * D;
                __syncthreads();
                for (int i = tid; i < 64 * 32; i += NTHR) {
                    int r = i >> 5, k4 = i & 31;
                    int gr = row0 + r;
                    float4 v = make_float4(0.f, 0.f, 0.f, 0.f);
                    if (gr < NN) v = *(const float4*)(Xc + (size_t)gr * D + k4 * 4);
                    *(float4*)(xs + r * D + k4 * 4) = v;
                }
                for (int kc = 0; kc < 8; kc++) {
                    __syncthreads();
                    for (int i = tid; i < 512; i += NTHR) {
                        int c = i & 127, k4 = i >> 7;
                        float4 w = *(const float4*)(Wc + (size_t)c * ldw + kc * 16 + k4 * 4);
                        ws[(k4 * 4 + 0) * D + c] = w.x;
                        ws[(k4 * 4 + 1) * D + c] = w.y;
                        ws[(k4 * 4 + 2) * D + c] = w.z;
                        ws[(k4 * 4 + 3) * D + c] = w.w;
                    }
                    __syncthreads();
#pragma unroll
                    for (int kk = 0; kk < 16; kk += 4)
                        mm_step(ws, xs, kk, kc * 16, r0, c0, acc);
                }
            }
            float4 bb = *(const float4*)(bias + c0);
#pragma unroll
            for (int j = 0; j < 8; j++) {
                int gr = row0 + r0 + j;
                if (gr >= NN) continue;
                float4 r = acc[j];
                r.x += bb.x; r.y += bb.y; r.z += bb.z; r.w += bb.w;
                *(float4*)(outp + (size_t)gr * D + c0) = r;
            }
        }
    }
    grid_barrier();

    // ---------------- P2: edge GEMM + gate epilogue ----------------
    {
        if (tid < D) { sA[tid] = 0.f; sB[tid] = 0.f; }
        __syncthreads();
        const int NTILE = NE / 64;   // 9375 exact
        for (int tile = bid; tile < NTILE; tile += NBLK) {
            int row0 = tile * 64;
            float4 acc[8];
#pragma unroll
            for (int j = 0; j < 8; j++) acc[j] = make_float4(0.f, 0.f, 0.f, 0.f);

            __syncthreads();
            for (int i = tid; i < 64 * 32; i += NTHR) {
                int r = i >> 5, k4 = i & 31;
                *(float4*)(xs + r * D + k4 * 4) =
                    *(const float4*)(e + (size_t)(row0 + r) * D + k4 * 4);
            }
            for (int kc = 0; kc < 8; kc++) {
                __syncthreads();
                for (int i = tid; i < 512; i += NTHR) {
                    int c = i & 127, k4 = i >> 7;
                    float4 w = *(const float4*)(B3w + (size_t)c * D + kc * 16 + k4 * 4);
                    ws[(k4 * 4 + 0) * D + c] = w.x;
                    ws[(k4 * 4 + 1) * D + c] = w.y;
                    ws[(k4 * 4 + 2) * D + c] = w.z;
                    ws[(k4 * 4 + 3) * D + c] = w.w;
                }
                __syncthreads();
#pragma unroll
                for (int kk = 0; kk < 16; kk += 4)
                    mm_step(ws, xs, kk, kc * 16, r0, c0, acc);
            }

            float4 bb = *(const float4*)(B3b + c0);
            float ps0 = 0.f, ps1 = 0.f, ps2 = 0.f, ps3 = 0.f;
            float pq0 = 0.f, pq1 = 0.f, pq2 = 0.f, pq3 = 0.f;
#pragma unroll
            for (int j = 0; j < 8; j++) {
                int er = row0 + r0 + j;
                int s_ = src[er];
                int t_ = dst[er];
                float4 g1 = *(const float4*)(g_b1h + (size_t)s_ * D + c0);
                float4 g2 = *(const float4*)(g_b2h + (size_t)t_ * D + c0);
                float4 r = acc[j];
                r.x += g1.x + g2.x + bb.x;
                r.y += g1.y + g2.y + bb.y;
                r.z += g1.z + g2.z + bb.z;
                r.w += g1.w + g2.w + bb.w;
                *(float4*)(ehat + (size_t)er * D + c0) = r;
                float* ssp = g_sum_sigma + (size_t)t_ * D + c0;
                atomicAdd(ssp + 0, sigf(r.x));
                atomicAdd(ssp + 1, sigf(r.y));
                atomicAdd(ssp + 2, sigf(r.z));
                atomicAdd(ssp + 3, sigf(r.w));
                ps0 += r.x; pq0 += r.x * r.x;
                ps1 += r.y; pq1 += r.y * r.y;
                ps2 += r.z; pq2 += r.z * r.z;
                ps3 += r.w; pq3 += r.w * r.w;
            }
            atomicAdd(&sA[c0 + 0], ps0); atomicAdd(&sB[c0 + 0], pq0);
            atomicAdd(&sA[c0 + 1], ps1); atomicAdd(&sB[c0 + 1], pq1);
            atomicAdd(&sA[c0 + 2], ps2); atomicAdd(&sB[c0 + 2], pq2);
            atomicAdd(&sA[c0 + 3], ps3); atomicAdd(&sB[c0 + 3], pq3);
        }
        __syncthreads();
        if (tid < D) {
            atomicAdd(&g_stats[tid], sA[tid]);
            atomicAdd(&g_stats[D + tid], sB[tid]);
        }
    }
    grid_barrier();

    // ---------------- P3: edge aggregation ----------------
    {
        int gw = bid * 8 + warp;
        int nw = NBLK * 8;
        int chunk = (NE + nw - 1) / nw;
        int e0 = gw * chunk;
        int e1 = e0 + chunk; if (e1 > NE) e1 = NE;
        for (int ei = e0; ei < e1; ei += 4) {
            int m = e1 - ei; if (m > 4) m = 4;
            int sj[4], tj[4];
            float4 hv[4], sv[4], vv[4], cv[4];
#pragma unroll
            for (int j = 0; j < 4; j++) if (j < m) { sj[j] = src[ei + j]; tj[j] = dst[ei + j]; }
#pragma unroll
            for (int j = 0; j < 4; j++) if (j < m)
                hv[j] = *(const float4*)(ehat + (size_t)(ei + j) * D + c0);
#pragma unroll
            for (int j = 0; j < 4; j++) if (j < m) {
                sv[j] = *(const float4*)(g_sum_sigma + (size_t)tj[j] * D + c0);
                vv[j] = *(const float4*)(g_v + (size_t)sj[j] * D + c0);
                cv[j] = *(const float4*)(g_c2p + (size_t)sj[j] * D + c0);
            }
#pragma unroll
            for (int j = 0; j < 4; j++) if (j < m) {
                float t0 = sigf(hv[j].x) / (sv[j].x + EPS_ETA);
                float t1 = sigf(hv[j].y) / (sv[j].y + EPS_ETA);
                float t2 = sigf(hv[j].z) / (sv[j].z + EPS_ETA);
                float t3 = sigf(hv[j].w) / (sv[j].w + EPS_ETA);
                float* ah = g_agg_h + (size_t)tj[j] * D + c0;
                atomicAdd(ah + 0, t0 * vv[j].x);
                atomicAdd(ah + 1, t1 * vv[j].y);
                atomicAdd(ah + 2, t2 * vv[j].z);
                atomicAdd(ah + 3, t3 * vv[j].w);
                float* ap = g_agg_p + (size_t)tj[j] * D + c0;
                atomicAdd(ap + 0, t0 * cv[j].x);
                atomicAdd(ap + 1, t1 * cv[j].y);
                atomicAdd(ap + 2, t2 * cv[j].z);
                atomicAdd(ap + 3, t3 * cv[j].w);
            }
        }
    }
    grid_barrier();

    // ---------------- P4: node finalize (h_new + h-stats, p_out) ----------------
    {
        if (tid < D) { sA[tid] = 0.f; sB[tid] = 0.f; }
        __syncthreads();
        int gw = bid * 8 + warp;
        int nw = NBLK * 8;
        float ps0 = 0.f, ps1 = 0.f, ps2 = 0.f, ps3 = 0.f;
        float pq0 = 0.f, pq1 = 0.f, pq2 = 0.f, pq3 = 0.f;
        for (int nid = gw; nid < NN; nid += nw) {
            size_t off = (size_t)nid * D + c0;
            float4 a = *(const float4*)(g_a1h + off);
            float4 g = *(const float4*)(g_agg_h + off);
            float4 hn = make_float4(a.x + g.x, a.y + g.y, a.z + g.z, a.w + g.w);
            *(float4*)(g_agg_h + off) = hn;
            ps0 += hn.x; pq0 += hn.x * hn.x;
            ps1 += hn.y; pq1 += hn.y * hn.y;
            ps2 += hn.z; pq2 += hn.z * hn.z;
            ps3 += hn.w; pq3 += hn.w * hn.w;

            float4 c1 = *(const float4*)(g_c1p + off);
            float4 gp = *(const float4*)(g_agg_p + off);
            float4 pv = *(const float4*)(p + off);
            float4 po;
            po.x = pv.x + tanhf(c1.x + gp.x);
            po.y = pv.y + tanhf(c1.y + gp.y);
            po.z = pv.z + tanhf(c1.z + gp.z);
            po.w = pv.w + tanhf(c1.w + gp.w);
            *(float4*)(p_out + off) = po;
        }
        atomicAdd(&sA[c0 + 0], ps0); atomicAdd(&sB[c0 + 0], pq0);
        atomicAdd(&sA[c0 + 1], ps1); atomicAdd(&sB[c0 + 1], pq1);
        atomicAdd(&sA[c0 + 2], ps2); atomicAdd(&sB[c0 + 2], pq2);
        atomicAdd(&sA[c0 + 3], ps3); atomicAdd(&sB[c0 + 3], pq3);
        __syncthreads();
        if (tid < D) {
            atomicAdd(&g_stats[2 * D + tid], sA[tid]);
            atomicAdd(&g_stats[3 * D + tid], sB[tid]);
        }
    }
    grid_barrier();

    // ---------------- P5: BN scale/shift (per-block, in ws) + finals ----------
    {
        if (tid < D) {
            float me = g_stats[tid] * (1.0f / NE);
            float ve = g_stats[D + tid] * (1.0f / NE) - me * me;
            float sce = bn_e_g[tid] * rsqrtf(ve + EPS_BN);
            ws[tid]       = sce;
            ws[D + tid]   = bn_e_b[tid] - me * sce;
            float mh = g_stats[2 * D + tid] * (1.0f / NN);
            float vh = g_stats[3 * D + tid] * (1.0f / NN) - mh * mh;
            float sch = bn_h_g[tid] * rsqrtf(vh + EPS_BN);
            ws[2 * D + tid] = sch;
            ws[3 * D + tid] = bn_h_b[tid] - mh * sch;
        }
        __syncthreads();

        // h_out = h + relu(bn(h_new))
        for (int i = gtid; i < NN * 32; i += gstr) {
            int c = (i & 31) * 4;
            float4 sc = *(float4*)(ws + 2 * D + c);
            float4 sh = *(float4*)(ws + 3 * D + c);
            float4 hn = ((const float4*)g_agg_h)[i];
            float4 hv = ((const float4*)h)[i];
            float4 o;
            o.x = hv.x + fmaxf(fmaf(hn.x, sc.x, sh.x), 0.f);
            o.y = hv.y + fmaxf(fmaf(hn.y, sc.y, sh.y), 0.f);
            o.z = hv.z + fmaxf(fmaf(hn.z, sc.z, sh.z), 0.f);
            o.w = hv.w + fmaxf(fmaf(hn.w, sc.w, sh.w), 0.f);
            ((float4*)h_out)[i] = o;
        }
        // e_out = e + relu(bn(hat))  (in place over hat)
        for (int i = gtid; i < NE * 32; i += gstr) {
            int c = (i & 31) * 4;
            float4 sc = *(float4*)(ws + c);
            float4 sh = *(float4*)(ws + D + c);
            float4 hn = ((const float4*)ehat)[i];
            float4 ev = ((const float4*)e)[i];
            float4 o;
            o.x = ev.x + fmaxf(fmaf(hn.x, sc.x, sh.x), 0.f);
            o.y = ev.y + fmaxf(fmaf(hn.y, sc.y, sh.y), 0.f);
            o.z = ev.z + fmaxf(fmaf(hn.z, sc.z, sh.z), 0.f);
            o.w = ev.w + fmaxf(fmaf(hn.w, sc.w, sh.w), 0.f);
            ((float4*)ehat)[i] = o;
        }
    }
}

// ---------------- launch -------------------------------------------------------
extern "C" void kernel_launch(void* const* d_in, const int* in_sizes, int n_in,
                              void* d_out, int out_size)
{
    const float* h   = (const float*)d_in[0];
    const float* e   = (const float*)d_in[1];
    const float* p   = (const float*)d_in[2];
    const int*   src = (const int*)d_in[3];
    const int*   dst = (const int*)d_in[4];
    const float* A1w = (const float*)d_in[5];
    const float* A1b = (const float*)d_in[6];
    const float* A2w = (const float*)d_in[7];
    const float* A2b = (const float*)d_in[8];
    const float* B1w = (const float*)d_in[9];
    const float* B1b = (const float*)d_in[10];
    const float* B2w = (const float*)d_in[11];
    const float* B2b = (const float*)d_in[12];
    const float* B3w = (const float*)d_in[13];
    const float* B3b = (const float*)d_in[14];
    const float* C1w = (const float*)d_in[15];
    const float* C1b = (const float*)d_in[16];
    const float* C2w = (const float*)d_in[17];
    const float* C2b = (const float*)d_in[18];
    const float* bn_h_g = (const float*)d_in[19];
    const float* bn_h_b = (const float*)d_in[20];
    const float* bn_e_g = (const float*)d_in[21];
    const float* bn_e_b = (const float*)d_in[22];

    float* out   = (float*)d_out;
    float* h_out = out;
    float* ehat  = out + (size_t)NN * D;
    float* p_out = out + (size_t)(NN + NE) * D;

    fused_gcn<<<NBLK, NTHR>>>(h, e, p, src, dst,
                              A1w, A1b, A2w, A2b,
                              B1w, B1b, B2w, B2b, B3w, B3b,
                              C1w, C1b, C2w, C2b,
                              bn_h_g, bn_h_b, bn_e_g, bn_e_b,
                              h_out, ehat, p_out);

    (void)in_sizes; (void)n_in; (void)out_size;
}

// round 5
// speedup vs baseline: 1.0389x; 1.0389x over previous
#include <cuda_runtime.h>
#include <math.h>

#define D       128
#define NN      50000
#define NE      600000
#define EPS_BN  1e-5f
#define EPS_ETA 1e-6f
#define NBLK    148
#define NTHR    256
#define CHUNK   338          // ceil(NN / NBLK)

// ---------------- device-global scratch (no allocations allowed) -------------
__device__ float g_b1h[NN * D];
__device__ float g_b2h[NN * D];
__device__ float g_a1h[NN * D];
__device__ float g_v[NN * D];
__device__ float g_c1p[NN * D];
__device__ float g_c2p[NN * D];
__device__ float g_agg_h[NN * D];     // h_new
__device__ float g_stats[4 * D];      // e_sum, e_sq, h_sum, h_sq
__device__ int   g_deg[NN];
__device__ int   g_start[NN];
__device__ int   g_cursor[NN];
__device__ int   g_eid[NE];
__device__ int   g_part[NBLK];
__device__ int            g_bar_count = 0;
__device__ volatile int   g_bar_gen   = 0;

__device__ __forceinline__ float sigf(float x) { return 1.0f / (1.0f + __expf(-x)); }

// ---------------- software grid barrier (all NBLK blocks co-resident) --------
__device__ __forceinline__ void grid_barrier()
{
    __syncthreads();
    if (threadIdx.x == 0) {
        int gen = g_bar_gen;
        __threadfence();
        if (atomicAdd(&g_bar_count, 1) == NBLK - 1) {
            g_bar_count = 0;
            __threadfence();
            g_bar_gen = gen + 1;
        } else {
            while (g_bar_gen == gen) { __nanosleep(64); }
        }
        __threadfence();
    }
    __syncthreads();
}

// ---------------- packed f32x2 helpers (sm_103a) -------------------------------
__device__ __forceinline__ unsigned long long pk2(float a, float b) {
    unsigned long long r;
    asm("mov.b64 %0, {%1, %2};" : "=l"(r) : "f"(a), "f"(b));
    return r;
}
__device__ __forceinline__ float2 upk2(unsigned long long v) {
    float2 r;
    asm("mov.b64 {%0, %1}, %2;" : "=f"(r.x), "=f"(r.y) : "l"(v));
    return r;
}
__device__ __forceinline__ unsigned long long ffma2(
    unsigned long long a, unsigned long long b, unsigned long long c) {
    unsigned long long d;
    asm("fma.rn.f32x2 %0, %1, %2, %3;" : "=l"(d) : "l"(a), "l"(b), "l"(c));
    return d;
}

// ---------------- FFMA2 micro-tile ----------------------------------------------
// ws: [16][128] k-major chunk; xs: [64][128]; 4 k-steps, 8 rows, 4 cols (2 pairs).
__device__ __forceinline__ void mm_step2(
    const float* ws, const float* xs,
    int kk, int kbase, int r0, int c0, unsigned long long acc[8][2])
{
    float4 w0 = *(const float4*)(ws + (kk + 0) * D + c0);
    float4 w1 = *(const float4*)(ws + (kk + 1) * D + c0);
    float4 w2 = *(const float4*)(ws + (kk + 2) * D + c0);
    float4 w3 = *(const float4*)(ws + (kk + 3) * D + c0);
    unsigned long long w0a = pk2(w0.x, w0.y), w0b = pk2(w0.z, w0.w);
    unsigned long long w1a = pk2(w1.x, w1.y), w1b = pk2(w1.z, w1.w);
    unsigned long long w2a = pk2(w2.x, w2.y), w2b = pk2(w2.z, w2.w);
    unsigned long long w3a = pk2(w3.x, w3.y), w3b = pk2(w3.z, w3.w);
#pragma unroll
    for (int j = 0; j < 8; j++) {
        float4 xv = *(const float4*)(xs + (r0 + j) * D + kbase + kk);
        unsigned long long b;
        b = pk2(xv.x, xv.x);
        acc[j][0] = ffma2(b, w0a, acc[j][0]);
        acc[j][1] = ffma2(b, w0b, acc[j][1]);
        b = pk2(xv.y, xv.y);
        acc[j][0] = ffma2(b, w1a, acc[j][0]);
        acc[j][1] = ffma2(b, w1b, acc[j][1]);
        b = pk2(xv.z, xv.z);
        acc[j][0] = ffma2(b, w2a, acc[j][0]);
        acc[j][1] = ffma2(b, w2b, acc[j][1]);
        b = pk2(xv.w, xv.w);
        acc[j][0] = ffma2(b, w3a, acc[j][0]);
        acc[j][1] = ffma2(b, w3b, acc[j][1]);
    }
}

// =============================================================================
// Single fused persistent kernel. grid = 148 x 256.
// =============================================================================
__global__ void __launch_bounds__(NTHR) fused_gcn(
    const float* __restrict__ h, const float* __restrict__ e, const float* __restrict__ p,
    const int* __restrict__ src, const int* __restrict__ dst,
    const float* __restrict__ A1w, const float* __restrict__ A1b,
    const float* __restrict__ A2w, const float* __restrict__ A2b,
    const float* __restrict__ B1w, const float* __restrict__ B1b,
    const float* __restrict__ B2w, const float* __restrict__ B2b,
    const float* __restrict__ B3w, const float* __restrict__ B3b,
    const float* __restrict__ C1w, const float* __restrict__ C1b,
    const float* __restrict__ C2w, const float* __restrict__ C2b,
    const float* __restrict__ bn_h_g, const float* __restrict__ bn_h_b,
    const float* __restrict__ bn_e_g, const float* __restrict__ bn_e_b,
    float* __restrict__ h_out, float* __restrict__ ehat, float* __restrict__ p_out)
{
    __shared__ __align__(16) float xs[64 * D];   // 32 KB (also scan buffers)
    __shared__ __align__(16) float ws[16 * D];   // 8 KB (also BN ss)
    __shared__ float sA[D];
    __shared__ float sB[D];
    __shared__ int s_off;

    const int tid  = threadIdx.x;
    const int lane = tid & 31;
    const int warp = tid >> 5;
    const int bid  = blockIdx.x;
    const int c0   = lane * 4;
    const int r0   = warp * 8;
    const int gtid = bid * NTHR + tid;
    const int gstr = NBLK * NTHR;

    // ---------------- Ph0: zero degree histogram + stats ----------------
    for (int i = gtid; i < NN; i += gstr) g_deg[i] = 0;
    if (gtid < 4 * D) g_stats[gtid] = 0.f;
    grid_barrier();

    // ---------------- PhA: degree histogram + node GEMMs ----------------
    for (int ei = gtid; ei < NE; ei += gstr) atomicAdd(&g_deg[dst[ei]], 1);
    {
        const int NTILE = (NN + 63) / 64;    // 782
        for (int job = bid; job < 6 * NTILE; job += NBLK) {
            int jid  = job / NTILE;
            int tile = job - jid * NTILE;
            int row0 = tile * 64;
            const float *X1 = h, *X2 = nullptr, *W = B1w, *bias = B1b;
            float* outp = g_b1h;
            int ldw = D, nhalf = 1;
            if      (jid == 1) { X1 = h; W = B2w; bias = B2b; outp = g_b2h; }
            else if (jid == 2) { X1 = h; W = A1w; bias = A1b; outp = g_a1h; }
            else if (jid == 3) { X1 = p; W = C1w; bias = C1b; outp = g_c1p; }
            else if (jid == 4) { X1 = p; W = C2w; bias = C2b; outp = g_c2p; }
            else if (jid == 5) { X1 = h; X2 = p; W = A2w; bias = A2b; outp = g_v; ldw = 2 * D; nhalf = 2; }

            unsigned long long acc[8][2];
#pragma unroll
            for (int j = 0; j < 8; j++) { acc[j][0] = 0ull; acc[j][1] = 0ull; }

            for (int half = 0; half < nhalf; half++) {
                const float* Xc = (half == 0) ? X1 : X2;
                const float* Wc = W + half * D;
                __syncthreads();
                for (int i = tid; i < 64 * 32; i += NTHR) {
                    int r = i >> 5, k4 = i & 31;
                    int gr = row0 + r;
                    float4 v = make_float4(0.f, 0.f, 0.f, 0.f);
                    if (gr < NN) v = *(const float4*)(Xc + (size_t)gr * D + k4 * 4);
                    *(float4*)(xs + r * D + k4 * 4) = v;
                }
                for (int kc = 0; kc < 8; kc++) {
                    __syncthreads();
                    for (int i = tid; i < 512; i += NTHR) {
                        int c = i & 127, k4 = i >> 7;
                        float4 w = *(const float4*)(Wc + (size_t)c * ldw + kc * 16 + k4 * 4);
                        ws[(k4 * 4 + 0) * D + c] = w.x;
                        ws[(k4 * 4 + 1) * D + c] = w.y;
                        ws[(k4 * 4 + 2) * D + c] = w.z;
                        ws[(k4 * 4 + 3) * D + c] = w.w;
                    }
                    __syncthreads();
#pragma unroll
                    for (int kk = 0; kk < 16; kk += 4)
                        mm_step2(ws, xs, kk, kc * 16, r0, c0, acc);
                }
            }
            float4 bb = *(const float4*)(bias + c0);
#pragma unroll
            for (int j = 0; j < 8; j++) {
                int gr = row0 + r0 + j;
                if (gr >= NN) continue;
                float2 lo = upk2(acc[j][0]);
                float2 hi = upk2(acc[j][1]);
                float4 r = make_float4(lo.x + bb.x, lo.y + bb.y, hi.x + bb.z, hi.y + bb.w);
                *(float4*)(outp + (size_t)gr * D + c0) = r;
            }
        }
    }
    grid_barrier();

    // ---------------- PhB: local exclusive scan of degrees, then edge GEMM ----
    {
        int base = bid * CHUNK;
        int cnt  = NN - base; if (cnt > CHUNK) cnt = CHUNK; if (cnt < 0) cnt = 0;
        int* sc  = (int*)xs;
        int* sc2 = sc + 512;
        for (int i = tid; i < 512; i += NTHR) sc[i] = (i < cnt) ? g_deg[base + i] : 0;
        __syncthreads();
        int* a = sc; int* b2 = sc2;
        for (int d0 = 1; d0 < 512; d0 <<= 1) {
            for (int i = tid; i < 512; i += NTHR) {
                int v = a[i];
                if (i >= d0) v += a[i - d0];
                b2[i] = v;
            }
            __syncthreads();
            int* t = a; a = b2; b2 = t;
        }
        for (int i = tid; i < cnt; i += NTHR)
            g_start[base + i] = a[i] - g_deg[base + i];   // exclusive, unoffset
        if (tid == 0) g_part[bid] = a[511];
        __syncthreads();
    }
    // edge GEMM: hat = B3 e + b3 + b1h[src] + b2h[dst]; write ehat; e-stats.
    {
        float ps0 = 0.f, ps1 = 0.f, ps2 = 0.f, ps3 = 0.f;
        float pq0 = 0.f, pq1 = 0.f, pq2 = 0.f, pq3 = 0.f;
        const int NTILE = NE / 64;   // 9375 exact
        for (int tile = bid; tile < NTILE; tile += NBLK) {
            int row0 = tile * 64;
            unsigned long long acc[8][2];
#pragma unroll
            for (int j = 0; j < 8; j++) { acc[j][0] = 0ull; acc[j][1] = 0ull; }

            __syncthreads();
            for (int i = tid; i < 64 * 32; i += NTHR) {
                int r = i >> 5, k4 = i & 31;
                *(float4*)(xs + r * D + k4 * 4) =
                    *(const float4*)(e + (size_t)(row0 + r) * D + k4 * 4);
            }
            for (int kc = 0; kc < 8; kc++) {
                __syncthreads();
                for (int i = tid; i < 512; i += NTHR) {
                    int c = i & 127, k4 = i >> 7;
                    float4 w = *(const float4*)(B3w + (size_t)c * D + kc * 16 + k4 * 4);
                    ws[(k4 * 4 + 0) * D + c] = w.x;
                    ws[(k4 * 4 + 1) * D + c] = w.y;
                    ws[(k4 * 4 + 2) * D + c] = w.z;
                    ws[(k4 * 4 + 3) * D + c] = w.w;
                }
                __syncthreads();
#pragma unroll
                for (int kk = 0; kk < 16; kk += 4)
                    mm_step2(ws, xs, kk, kc * 16, r0, c0, acc);
            }

            float4 bb = *(const float4*)(B3b + c0);
#pragma unroll
            for (int j = 0; j < 8; j++) {
                int er = row0 + r0 + j;
                int s_ = src[er];
                int t_ = dst[er];
                float4 g1 = *(const float4*)(g_b1h + (size_t)s_ * D + c0);
                float4 g2 = *(const float4*)(g_b2h + (size_t)t_ * D + c0);
                float2 lo = upk2(acc[j][0]);
                float2 hi = upk2(acc[j][1]);
                float4 r;
                r.x = lo.x + g1.x + g2.x + bb.x;
                r.y = lo.y + g1.y + g2.y + bb.y;
                r.z = hi.x + g1.z + g2.z + bb.z;
                r.w = hi.y + g1.w + g2.w + bb.w;
                *(float4*)(ehat + (size_t)er * D + c0) = r;
                ps0 += r.x; pq0 += r.x * r.x;
                ps1 += r.y; pq1 += r.y * r.y;
                ps2 += r.z; pq2 += r.z * r.z;
                ps3 += r.w; pq3 += r.w * r.w;
            }
        }
        if (tid < D) { sA[tid] = 0.f; sB[tid] = 0.f; }
        __syncthreads();
        atomicAdd(&sA[c0 + 0], ps0); atomicAdd(&sB[c0 + 0], pq0);
        atomicAdd(&sA[c0 + 1], ps1); atomicAdd(&sB[c0 + 1], pq1);
        atomicAdd(&sA[c0 + 2], ps2); atomicAdd(&sB[c0 + 2], pq2);
        atomicAdd(&sA[c0 + 3], ps3); atomicAdd(&sB[c0 + 3], pq3);
        __syncthreads();
        if (tid < D) {
            atomicAdd(&g_stats[tid], sA[tid]);
            atomicAdd(&g_stats[D + tid], sB[tid]);
        }
    }
    grid_barrier();

    // ---------------- PhC: add global offsets to starts, init cursors ---------
    {
        int* sp = (int*)xs;
        for (int i = tid; i < NBLK; i += NTHR) sp[i] = g_part[i];
        __syncthreads();
        if (tid == 0) {
            int o = 0;
            for (int i = 0; i < bid; i++) o += sp[i];
            s_off = o;
        }
        __syncthreads();
        int off  = s_off;
        int base = bid * CHUNK;
        int cnt  = NN - base; if (cnt > CHUNK) cnt = CHUNK; if (cnt < 0) cnt = 0;
        for (int i = tid; i < cnt; i += NTHR) {
            int v = g_start[base + i] + off;
            g_start[base + i]  = v;
            g_cursor[base + i] = v;
        }
    }
    grid_barrier();

    // ---------------- PhD: scatter edge ids by dst ----------------
    for (int ei = gtid; ei < NE; ei += gstr) {
        int t_  = dst[ei];
        int pos = atomicAdd(&g_cursor[t_], 1);
        g_eid[pos] = ei;
    }
    grid_barrier();

    // ---------------- PhE: warp-per-node aggregation + node finalize ----------
    {
        if (tid < D) { sA[tid] = 0.f; sB[tid] = 0.f; }
        __syncthreads();
        const int gw = bid * 8 + warp;
        const int NW = NBLK * 8;
        float ps0 = 0.f, ps1 = 0.f, ps2 = 0.f, ps3 = 0.f;
        float pq0 = 0.f, pq1 = 0.f, pq2 = 0.f, pq3 = 0.f;

        for (int n = gw; n < NN; n += NW) {
            int st = g_start[n];
            int dg = g_deg[n];
            float4 ss = make_float4(0.f, 0.f, 0.f, 0.f);
            for (int i = 0; i < dg; i++) {
                int eid = g_eid[st + i];
                float4 hv = *(const float4*)(ehat + (size_t)eid * D + c0);
                ss.x += sigf(hv.x);
                ss.y += sigf(hv.y);
                ss.z += sigf(hv.z);
                ss.w += sigf(hv.w);
            }
            float i0 = 1.0f / (ss.x + EPS_ETA);
            float i1 = 1.0f / (ss.y + EPS_ETA);
            float i2 = 1.0f / (ss.z + EPS_ETA);
            float i3 = 1.0f / (ss.w + EPS_ETA);
            float4 ah = make_float4(0.f, 0.f, 0.f, 0.f);
            float4 ap = make_float4(0.f, 0.f, 0.f, 0.f);
            for (int i = 0; i < dg; i++) {
                int eid = g_eid[st + i];
                int s_  = src[eid];
                float4 hv = *(const float4*)(ehat + (size_t)eid * D + c0);
                float e0 = sigf(hv.x) * i0;
                float e1 = sigf(hv.y) * i1;
                float e2 = sigf(hv.z) * i2;
                float e3 = sigf(hv.w) * i3;
                float4 vv = *(const float4*)(g_v + (size_t)s_ * D + c0);
                float4 cp = *(const float4*)(g_c2p + (size_t)s_ * D + c0);
                ah.x = fmaf(e0, vv.x, ah.x);
                ah.y = fmaf(e1, vv.y, ah.y);
                ah.z = fmaf(e2, vv.z, ah.z);
                ah.w = fmaf(e3, vv.w, ah.w);
                ap.x = fmaf(e0, cp.x, ap.x);
                ap.y = fmaf(e1, cp.y, ap.y);
                ap.z = fmaf(e2, cp.z, ap.z);
                ap.w = fmaf(e3, cp.w, ap.w);
            }
            size_t off = (size_t)n * D + c0;
            float4 a1 = *(const float4*)(g_a1h + off);
            float4 hn = make_float4(a1.x + ah.x, a1.y + ah.y, a1.z + ah.z, a1.w + ah.w);
            *(float4*)(g_agg_h + off) = hn;
            ps0 += hn.x; pq0 += hn.x * hn.x;
            ps1 += hn.y; pq1 += hn.y * hn.y;
            ps2 += hn.z; pq2 += hn.z * hn.z;
            ps3 += hn.w; pq3 += hn.w * hn.w;

            float4 c1 = *(const float4*)(g_c1p + off);
            float4 pv = *(const float4*)(p + off);
            float4 po;
            po.x = pv.x + tanhf(c1.x + ap.x);
            po.y = pv.y + tanhf(c1.y + ap.y);
            po.z = pv.z + tanhf(c1.z + ap.z);
            po.w = pv.w + tanhf(c1.w + ap.w);
            *(float4*)(p_out + off) = po;
        }
        atomicAdd(&sA[c0 + 0], ps0); atomicAdd(&sB[c0 + 0], pq0);
        atomicAdd(&sA[c0 + 1], ps1); atomicAdd(&sB[c0 + 1], pq1);
        atomicAdd(&sA[c0 + 2], ps2); atomicAdd(&sB[c0 + 2], pq2);
        atomicAdd(&sA[c0 + 3], ps3); atomicAdd(&sB[c0 + 3], pq3);
        __syncthreads();
        if (tid < D) {
            atomicAdd(&g_stats[2 * D + tid], sA[tid]);
            atomicAdd(&g_stats[3 * D + tid], sB[tid]);
        }
    }
    grid_barrier();

    // ---------------- PhF: BN scale/shift + final streams ----------------
    {
        if (tid < D) {
            float me  = g_stats[tid] * (1.0f / NE);
            float ve  = g_stats[D + tid] * (1.0f / NE) - me * me;
            float sce = bn_e_g[tid] * rsqrtf(ve + EPS_BN);
            ws[tid]         = sce;
            ws[D + tid]     = bn_e_b[tid] - me * sce;
            float mh  = g_stats[2 * D + tid] * (1.0f / NN);
            float vh  = g_stats[3 * D + tid] * (1.0f / NN) - mh * mh;
            float sch = bn_h_g[tid] * rsqrtf(vh + EPS_BN);
            ws[2 * D + tid] = sch;
            ws[3 * D + tid] = bn_h_b[tid] - mh * sch;
        }
        __syncthreads();

        // h_out = h + relu(bn(h_new))
        for (int i = gtid; i < NN * 32; i += gstr) {
            int c = (i & 31) * 4;
            float4 sc = *(float4*)(ws + 2 * D + c);
            float4 sh = *(float4*)(ws + 3 * D + c);
            float4 hn = ((const float4*)g_agg_h)[i];
            float4 hv = ((const float4*)h)[i];
            float4 o;
            o.x = hv.x + fmaxf(fmaf(hn.x, sc.x, sh.x), 0.f);
            o.y = hv.y + fmaxf(fmaf(hn.y, sc.y, sh.y), 0.f);
            o.z = hv.z + fmaxf(fmaf(hn.z, sc.z, sh.z), 0.f);
            o.w = hv.w + fmaxf(fmaf(hn.w, sc.w, sh.w), 0.f);
            ((float4*)h_out)[i] = o;
        }
        // e_out = e + relu(bn(hat))  (in place over ehat)
        for (int i = gtid; i < NE * 32; i += gstr) {
            int c = (i & 31) * 4;
            float4 sc = *(float4*)(ws + c);
            float4 sh = *(float4*)(ws + D + c);
            float4 hn = ((const float4*)ehat)[i];
            float4 ev = ((const float4*)e)[i];
            float4 o;
            o.x = ev.x + fmaxf(fmaf(hn.x, sc.x, sh.x), 0.f);
            o.y = ev.y + fmaxf(fmaf(hn.y, sc.y, sh.y), 0.f);
            o.z = ev.z + fmaxf(fmaf(hn.z, sc.z, sh.z), 0.f);
            o.w = ev.w + fmaxf(fmaf(hn.w, sc.w, sh.w), 0.f);
            ((float4*)ehat)[i] = o;
        }
    }
}

// ---------------- launch -------------------------------------------------------
extern "C" void kernel_launch(void* const* d_in, const int* in_sizes, int n_in,
                              void* d_out, int out_size)
{
    const float* h   = (const float*)d_in[0];
    const float* e   = (const float*)d_in[1];
    const float* p   = (const float*)d_in[2];
    const int*   src = (const int*)d_in[3];
    const int*   dst = (const int*)d_in[4];
    const float* A1w = (const float*)d_in[5];
    const float* A1b = (const float*)d_in[6];
    const float* A2w = (const float*)d_in[7];
    const float* A2b = (const float*)d_in[8];
    const float* B1w = (const float*)d_in[9];
    const float* B1b = (const float*)d_in[10];
    const float* B2w = (const float*)d_in[11];
    const float* B2b = (const float*)d_in[12];
    const float* B3w = (const float*)d_in[13];
    const float* B3b = (const float*)d_in[14];
    const float* C1w = (const float*)d_in[15];
    const float* C1b = (const float*)d_in[16];
    const float* C2w = (const float*)d_in[17];
    const float* C2b = (const float*)d_in[18];
    const float* bn_h_g = (const float*)d_in[19];
    const float* bn_h_b = (const float*)d_in[20];
    const float* bn_e_g = (const float*)d_in[21];
    const float* bn_e_b = (const float*)d_in[22];

    float* out   = (float*)d_out;
    float* h_out = out;
    float* ehat  = out + (size_t)NN * D;
    float* p_out = out + (size_t)(NN + NE) * D;

    fused_gcn<<<NBLK, NTHR>>>(h, e, p, src, dst,
                              A1w, A1b, A2w, A2b,
                              B1w, B1b, B2w, B2b, B3w, B3b,
                              C1w, C1b, C2w, C2b,
                              bn_h_g, bn_h_b, bn_e_g, bn_e_b,
                              h_out, ehat, p_out);

    (void)in_sizes; (void)n_in; (void)out_size;
}

// round 6
// speedup vs baseline: 1.4547x; 1.4002x over previous
#include <cuda_runtime.h>
#include <math.h>

#define D       128
#define NN      50000
#define NE      600000
#define EPS_BN  1e-5f
#define EPS_ETA 1e-6f
#define NBLK    148
#define NTHR    512
#define NWARP   16
#define CHUNK   338          // ceil(NN / NBLK)

// ---------------- device-global scratch (no allocations allowed) -------------
__device__ float g_b1h[NN * D];
__device__ float g_b2h[NN * D];
__device__ float g_a1h[NN * D];
__device__ float g_v[NN * D];
__device__ float g_c1p[NN * D];
__device__ float g_c2p[NN * D];
__device__ float g_agg_h[NN * D];     // h_new
__device__ float g_stats[4 * D];      // e_sum, e_sq, h_sum, h_sq
__device__ int   g_deg[NN];
__device__ int   g_start[NN];
__device__ int   g_cursor[NN];
__device__ int   g_eid[NE];
__device__ int   g_part[NBLK];
__device__ int            g_bar_count = 0;
__device__ volatile int   g_bar_gen   = 0;

__device__ __forceinline__ float sigf(float x) { return 1.0f / (1.0f + __expf(-x)); }

// ---------------- software grid barrier (all NBLK blocks co-resident) --------
__device__ __forceinline__ void grid_barrier()
{
    __syncthreads();
    if (threadIdx.x == 0) {
        int gen = g_bar_gen;
        __threadfence();
        if (atomicAdd(&g_bar_count, 1) == NBLK - 1) {
            g_bar_count = 0;
            __threadfence();
            g_bar_gen = gen + 1;
        } else {
            while (g_bar_gen == gen) { __nanosleep(64); }
        }
        __threadfence();
    }
    __syncthreads();
}

// ---------------- packed f32x2 helpers (sm_103a) -------------------------------
__device__ __forceinline__ unsigned long long pk2(float a, float b) {
    unsigned long long r;
    asm("mov.b64 %0, {%1, %2};" : "=l"(r) : "f"(a), "f"(b));
    return r;
}
__device__ __forceinline__ float2 upk2(unsigned long long v) {
    float2 r;
    asm("mov.b64 {%0, %1}, %2;" : "=f"(r.x), "=f"(r.y) : "l"(v));
    return r;
}
__device__ __forceinline__ unsigned long long ffma2(
    unsigned long long a, unsigned long long b, unsigned long long c) {
    unsigned long long d;
    asm("fma.rn.f32x2 %0, %1, %2, %3;" : "=l"(d) : "l"(a), "l"(b), "l"(c));
    return d;
}

// ---------------- FFMA2 micro-tile ----------------------------------------------
// ws: [16][128] k-major chunk; xs: [64][128]; 4 k-steps, 4 rows, 4 cols (2 pairs).
__device__ __forceinline__ void mm_step2(
    const float* ws, const float* xs,
    int kk, int kbase, int r0, int c0, unsigned long long acc[4][2])
{
    float4 w0 = *(const float4*)(ws + (kk + 0) * D + c0);
    float4 w1 = *(const float4*)(ws + (kk + 1) * D + c0);
    float4 w2 = *(const float4*)(ws + (kk + 2) * D + c0);
    float4 w3 = *(const float4*)(ws + (kk + 3) * D + c0);
    unsigned long long w0a = pk2(w0.x, w0.y), w0b = pk2(w0.z, w0.w);
    unsigned long long w1a = pk2(w1.x, w1.y), w1b = pk2(w1.z, w1.w);
    unsigned long long w2a = pk2(w2.x, w2.y), w2b = pk2(w2.z, w2.w);
    unsigned long long w3a = pk2(w3.x, w3.y), w3b = pk2(w3.z, w3.w);
#pragma unroll
    for (int j = 0; j < 4; j++) {
        float4 xv = *(const float4*)(xs + (r0 + j) * D + kbase + kk);
        unsigned long long b;
        b = pk2(xv.x, xv.x);
        acc[j][0] = ffma2(b, w0a, acc[j][0]);
        acc[j][1] = ffma2(b, w0b, acc[j][1]);
        b = pk2(xv.y, xv.y);
        acc[j][0] = ffma2(b, w1a, acc[j][0]);
        acc[j][1] = ffma2(b, w1b, acc[j][1]);
        b = pk2(xv.z, xv.z);
        acc[j][0] = ffma2(b, w2a, acc[j][0]);
        acc[j][1] = ffma2(b, w2b, acc[j][1]);
        b = pk2(xv.w, xv.w);
        acc[j][0] = ffma2(b, w3a, acc[j][0]);
        acc[j][1] = ffma2(b, w3b, acc[j][1]);
    }
}

// =============================================================================
// Single fused persistent kernel. grid = 148 x 512.
// =============================================================================
__global__ void __launch_bounds__(NTHR) fused_gcn(
    const float* __restrict__ h, const float* __restrict__ e, const float* __restrict__ p,
    const int* __restrict__ src, const int* __restrict__ dst,
    const float* __restrict__ A1w, const float* __restrict__ A1b,
    const float* __restrict__ A2w, const float* __restrict__ A2b,
    const float* __restrict__ B1w, const float* __restrict__ B1b,
    const float* __restrict__ B2w, const float* __restrict__ B2b,
    const float* __restrict__ B3w, const float* __restrict__ B3b,
    const float* __restrict__ C1w, const float* __restrict__ C1b,
    const float* __restrict__ C2w, const float* __restrict__ C2b,
    const float* __restrict__ bn_h_g, const float* __restrict__ bn_h_b,
    const float* __restrict__ bn_e_g, const float* __restrict__ bn_e_b,
    float* __restrict__ h_out, float* __restrict__ ehat, float* __restrict__ p_out)
{
    __shared__ __align__(16) float xs[64 * D];   // 32 KB (also scan buffers)
    __shared__ __align__(16) float ws[16 * D];   // 8 KB (also BN ss)
    __shared__ float sA[D];
    __shared__ float sB[D];
    __shared__ int s_off;

    const int tid  = threadIdx.x;
    const int lane = tid & 31;
    const int warp = tid >> 5;
    const int bid  = blockIdx.x;
    const int c0   = lane * 4;
    const int r0   = warp * 4;
    const int gtid = bid * NTHR + tid;
    const int gstr = NBLK * NTHR;

    // ---------------- Ph0: zero degree histogram + stats ----------------
    for (int i = gtid; i < NN; i += gstr) g_deg[i] = 0;
    if (gtid < 4 * D) g_stats[gtid] = 0.f;
    grid_barrier();

    // ---------------- PhA: degree histogram + node GEMMs ----------------
    for (int ei = gtid; ei < NE; ei += gstr) atomicAdd(&g_deg[dst[ei]], 1);
    {
        const int NTILE = (NN + 63) / 64;    // 782
        for (int job = bid; job < 6 * NTILE; job += NBLK) {
            int jid  = job / NTILE;
            int tile = job - jid * NTILE;
            int row0 = tile * 64;
            const float *X1 = h, *X2 = nullptr, *W = B1w, *bias = B1b;
            float* outp = g_b1h;
            int ldw = D, nhalf = 1;
            if      (jid == 1) { X1 = h; W = B2w; bias = B2b; outp = g_b2h; }
            else if (jid == 2) { X1 = h; W = A1w; bias = A1b; outp = g_a1h; }
            else if (jid == 3) { X1 = p; W = C1w; bias = C1b; outp = g_c1p; }
            else if (jid == 4) { X1 = p; W = C2w; bias = C2b; outp = g_c2p; }
            else if (jid == 5) { X1 = h; X2 = p; W = A2w; bias = A2b; outp = g_v; ldw = 2 * D; nhalf = 2; }

            unsigned long long acc[4][2];
#pragma unroll
            for (int j = 0; j < 4; j++) { acc[j][0] = 0ull; acc[j][1] = 0ull; }

            for (int half = 0; half < nhalf; half++) {
                const float* Xc = (half == 0) ? X1 : X2;
                const float* Wc = W + half * D;
                __syncthreads();
                for (int i = tid; i < 64 * 32; i += NTHR) {
                    int r = i >> 5, k4 = i & 31;
                    int gr = row0 + r;
                    float4 v = make_float4(0.f, 0.f, 0.f, 0.f);
                    if (gr < NN) v = *(const float4*)(Xc + (size_t)gr * D + k4 * 4);
                    *(float4*)(xs + r * D + k4 * 4) = v;
                }
                for (int kc = 0; kc < 8; kc++) {
                    __syncthreads();
                    for (int i = tid; i < 512; i += NTHR) {
                        int c = i & 127, k4 = i >> 7;
                        float4 w = *(const float4*)(Wc + (size_t)c * ldw + kc * 16 + k4 * 4);
                        ws[(k4 * 4 + 0) * D + c] = w.x;
                        ws[(k4 * 4 + 1) * D + c] = w.y;
                        ws[(k4 * 4 + 2) * D + c] = w.z;
                        ws[(k4 * 4 + 3) * D + c] = w.w;
                    }
                    __syncthreads();
#pragma unroll
                    for (int kk = 0; kk < 16; kk += 4)
                        mm_step2(ws, xs, kk, kc * 16, r0, c0, acc);
                }
            }
            float4 bb = *(const float4*)(bias + c0);
#pragma unroll
            for (int j = 0; j < 4; j++) {
                int gr = row0 + r0 + j;
                if (gr >= NN) continue;
                float2 lo = upk2(acc[j][0]);
                float2 hi = upk2(acc[j][1]);
                float4 r = make_float4(lo.x + bb.x, lo.y + bb.y, hi.x + bb.z, hi.y + bb.w);
                *(float4*)(outp + (size_t)gr * D + c0) = r;
            }
        }
    }
    grid_barrier();

    // ---------------- PhB: local exclusive scan of degrees, then edge GEMM ----
    {
        int base = bid * CHUNK;
        int cnt  = NN - base; if (cnt > CHUNK) cnt = CHUNK; if (cnt < 0) cnt = 0;
        int* sc  = (int*)xs;
        int* sc2 = sc + 512;
        for (int i = tid; i < 512; i += NTHR) sc[i] = (i < cnt) ? g_deg[base + i] : 0;
        __syncthreads();
        int* a = sc; int* b2 = sc2;
        for (int d0 = 1; d0 < 512; d0 <<= 1) {
            for (int i = tid; i < 512; i += NTHR) {
                int v = a[i];
                if (i >= d0) v += a[i - d0];
                b2[i] = v;
            }
            __syncthreads();
            int* t = a; a = b2; b2 = t;
        }
        for (int i = tid; i < cnt; i += NTHR)
            g_start[base + i] = a[i] - g_deg[base + i];   // exclusive, unoffset
        if (tid == 0) g_part[bid] = a[511];
        __syncthreads();
    }
    // edge GEMM: hat = B3 e + b3 + b1h[src] + b2h[dst]; write ehat; e-stats.
    {
        float ps0 = 0.f, ps1 = 0.f, ps2 = 0.f, ps3 = 0.f;
        float pq0 = 0.f, pq1 = 0.f, pq2 = 0.f, pq3 = 0.f;
        const int NTILE = NE / 64;   // 9375 exact
        for (int tile = bid; tile < NTILE; tile += NBLK) {
            int row0 = tile * 64;
            unsigned long long acc[4][2];
#pragma unroll
            for (int j = 0; j < 4; j++) { acc[j][0] = 0ull; acc[j][1] = 0ull; }

            __syncthreads();
            for (int i = tid; i < 64 * 32; i += NTHR) {
                int r = i >> 5, k4 = i & 31;
                *(float4*)(xs + r * D + k4 * 4) =
                    *(const float4*)(e + (size_t)(row0 + r) * D + k4 * 4);
            }
            for (int kc = 0; kc < 8; kc++) {
                __syncthreads();
                for (int i = tid; i < 512; i += NTHR) {
                    int c = i & 127, k4 = i >> 7;
                    float4 w = *(const float4*)(B3w + (size_t)c * D + kc * 16 + k4 * 4);
                    ws[(k4 * 4 + 0) * D + c] = w.x;
                    ws[(k4 * 4 + 1) * D + c] = w.y;
                    ws[(k4 * 4 + 2) * D + c] = w.z;
                    ws[(k4 * 4 + 3) * D + c] = w.w;
                }
                __syncthreads();
#pragma unroll
                for (int kk = 0; kk < 16; kk += 4)
                    mm_step2(ws, xs, kk, kc * 16, r0, c0, acc);
            }

            float4 bb = *(const float4*)(B3b + c0);
#pragma unroll
            for (int j = 0; j < 4; j++) {
                int er = row0 + r0 + j;
                int s_ = src[er];
                int t_ = dst[er];
                float4 g1 = *(const float4*)(g_b1h + (size_t)s_ * D + c0);
                float4 g2 = *(const float4*)(g_b2h + (size_t)t_ * D + c0);
                float2 lo = upk2(acc[j][0]);
                float2 hi = upk2(acc[j][1]);
                float4 r;
                r.x = lo.x + g1.x + g2.x + bb.x;
                r.y = lo.y + g1.y + g2.y + bb.y;
                r.z = hi.x + g1.z + g2.z + bb.z;
                r.w = hi.y + g1.w + g2.w + bb.w;
                *(float4*)(ehat + (size_t)er * D + c0) = r;
                ps0 += r.x; pq0 += r.x * r.x;
                ps1 += r.y; pq1 += r.y * r.y;
                ps2 += r.z; pq2 += r.z * r.z;
                ps3 += r.w; pq3 += r.w * r.w;
            }
        }
        if (tid < D) { sA[tid] = 0.f; sB[tid] = 0.f; }
        __syncthreads();
        atomicAdd(&sA[c0 + 0], ps0); atomicAdd(&sB[c0 + 0], pq0);
        atomicAdd(&sA[c0 + 1], ps1); atomicAdd(&sB[c0 + 1], pq1);
        atomicAdd(&sA[c0 + 2], ps2); atomicAdd(&sB[c0 + 2], pq2);
        atomicAdd(&sA[c0 + 3], ps3); atomicAdd(&sB[c0 + 3], pq3);
        __syncthreads();
        if (tid < D) {
            atomicAdd(&g_stats[tid], sA[tid]);
            atomicAdd(&g_stats[D + tid], sB[tid]);
        }
    }
    grid_barrier();

    // ---------------- PhC: add global offsets to starts, init cursors ---------
    {
        int* sp = (int*)xs;
        for (int i = tid; i < NBLK; i += NTHR) sp[i] = g_part[i];
        __syncthreads();
        if (tid == 0) {
            int o = 0;
            for (int i = 0; i < bid; i++) o += sp[i];
            s_off = o;
        }
        __syncthreads();
        int off  = s_off;
        int base = bid * CHUNK;
        int cnt  = NN - base; if (cnt > CHUNK) cnt = CHUNK; if (cnt < 0) cnt = 0;
        for (int i = tid; i < cnt; i += NTHR) {
            int v = g_start[base + i] + off;
            g_start[base + i]  = v;
            g_cursor[base + i] = v;
        }
    }
    grid_barrier();

    // ---------------- PhD: scatter edge ids by dst ----------------
    for (int ei = gtid; ei < NE; ei += gstr) {
        int t_  = dst[ei];
        int pos = atomicAdd(&g_cursor[t_], 1);
        g_eid[pos] = ei;
    }
    grid_barrier();

    // ---------------- PhE: warp-per-node single-pass aggregation + finalize ---
    // eta = sigma/(S+eps)  =>  sum(eta*v) = sum(sigma*v) / (S+eps)
    {
        if (tid < D) { sA[tid] = 0.f; sB[tid] = 0.f; }
        __syncthreads();
        const int gw = bid * NWARP + warp;
        const int NW = NBLK * NWARP;
        float ps0 = 0.f, ps1 = 0.f, ps2 = 0.f, ps3 = 0.f;
        float pq0 = 0.f, pq1 = 0.f, pq2 = 0.f, pq3 = 0.f;

        for (int n = gw; n < NN; n += NW) {
            int st = g_start[n];
            int dg = g_deg[n];
            float4 ss = make_float4(0.f, 0.f, 0.f, 0.f);
            float4 ah = make_float4(0.f, 0.f, 0.f, 0.f);
            float4 ap = make_float4(0.f, 0.f, 0.f, 0.f);
#pragma unroll 2
            for (int i = 0; i < dg; i++) {
                int eid = g_eid[st + i];
                int s_  = src[eid];
                float4 hv = *(const float4*)(ehat + (size_t)eid * D + c0);
                float4 vv = *(const float4*)(g_v + (size_t)s_ * D + c0);
                float4 cp = *(const float4*)(g_c2p + (size_t)s_ * D + c0);
                float s0 = sigf(hv.x), s1 = sigf(hv.y), s2 = sigf(hv.z), s3 = sigf(hv.w);
                ss.x += s0; ss.y += s1; ss.z += s2; ss.w += s3;
                ah.x = fmaf(s0, vv.x, ah.x);
                ah.y = fmaf(s1, vv.y, ah.y);
                ah.z = fmaf(s2, vv.z, ah.z);
                ah.w = fmaf(s3, vv.w, ah.w);
                ap.x = fmaf(s0, cp.x, ap.x);
                ap.y = fmaf(s1, cp.y, ap.y);
                ap.z = fmaf(s2, cp.z, ap.z);
                ap.w = fmaf(s3, cp.w, ap.w);
            }
            float i0 = 1.0f / (ss.x + EPS_ETA);
            float i1 = 1.0f / (ss.y + EPS_ETA);
            float i2 = 1.0f / (ss.z + EPS_ETA);
            float i3 = 1.0f / (ss.w + EPS_ETA);

            size_t off = (size_t)n * D + c0;
            float4 a1 = *(const float4*)(g_a1h + off);
            float4 hn = make_float4(fmaf(ah.x, i0, a1.x), fmaf(ah.y, i1, a1.y),
                                    fmaf(ah.z, i2, a1.z), fmaf(ah.w, i3, a1.w));
            *(float4*)(g_agg_h + off) = hn;
            ps0 += hn.x; pq0 += hn.x * hn.x;
            ps1 += hn.y; pq1 += hn.y * hn.y;
            ps2 += hn.z; pq2 += hn.z * hn.z;
            ps3 += hn.w; pq3 += hn.w * hn.w;

            float4 c1 = *(const float4*)(g_c1p + off);
            float4 pv = *(const float4*)(p + off);
            float4 po;
            po.x = pv.x + tanhf(fmaf(ap.x, i0, c1.x));
            po.y = pv.y + tanhf(fmaf(ap.y, i1, c1.y));
            po.z = pv.z + tanhf(fmaf(ap.z, i2, c1.z));
            po.w = pv.w + tanhf(fmaf(ap.w, i3, c1.w));
            *(float4*)(p_out + off) = po;
        }
        atomicAdd(&sA[c0 + 0], ps0); atomicAdd(&sB[c0 + 0], pq0);
        atomicAdd(&sA[c0 + 1], ps1); atomicAdd(&sB[c0 + 1], pq1);
        atomicAdd(&sA[c0 + 2], ps2); atomicAdd(&sB[c0 + 2], pq2);
        atomicAdd(&sA[c0 + 3], ps3); atomicAdd(&sB[c0 + 3], pq3);
        __syncthreads();
        if (tid < D) {
            atomicAdd(&g_stats[2 * D + tid], sA[tid]);
            atomicAdd(&g_stats[3 * D + tid], sB[tid]);
        }
    }
    grid_barrier();

    // ---------------- PhF: BN scale/shift + final streams ----------------
    {
        if (tid < D) {
            float me  = g_stats[tid] * (1.0f / NE);
            float ve  = g_stats[D + tid] * (1.0f / NE) - me * me;
            float sce = bn_e_g[tid] * rsqrtf(ve + EPS_BN);
            ws[tid]         = sce;
            ws[D + tid]     = bn_e_b[tid] - me * sce;
            float mh  = g_stats[2 * D + tid] * (1.0f / NN);
            float vh  = g_stats[3 * D + tid] * (1.0f / NN) - mh * mh;
            float sch = bn_h_g[tid] * rsqrtf(vh + EPS_BN);
            ws[2 * D + tid] = sch;
            ws[3 * D + tid] = bn_h_b[tid] - mh * sch;
        }
        __syncthreads();

        // h_out = h + relu(bn(h_new))
        for (int i = gtid; i < NN * 32; i += gstr) {
            int c = (i & 31) * 4;
            float4 sc = *(float4*)(ws + 2 * D + c);
            float4 sh = *(float4*)(ws + 3 * D + c);
            float4 hn = ((const float4*)g_agg_h)[i];
            float4 hv = ((const float4*)h)[i];
            float4 o;
            o.x = hv.x + fmaxf(fmaf(hn.x, sc.x, sh.x), 0.f);
            o.y = hv.y + fmaxf(fmaf(hn.y, sc.y, sh.y), 0.f);
            o.z = hv.z + fmaxf(fmaf(hn.z, sc.z, sh.z), 0.f);
            o.w = hv.w + fmaxf(fmaf(hn.w, sc.w, sh.w), 0.f);
            ((float4*)h_out)[i] = o;
        }
        // e_out = e + relu(bn(hat))  (in place over ehat)
        for (int i = gtid; i < NE * 32; i += gstr) {
            int c = (i & 31) * 4;
            float4 sc = *(float4*)(ws + c);
            float4 sh = *(float4*)(ws + D + c);
            float4 hn = ((const float4*)ehat)[i];
            float4 ev = ((const float4*)e)[i];
            float4 o;
            o.x = ev.x + fmaxf(fmaf(hn.x, sc.x, sh.x), 0.f);
            o.y = ev.y + fmaxf(fmaf(hn.y, sc.y, sh.y), 0.f);
            o.z = ev.z + fmaxf(fmaf(hn.z, sc.z, sh.z), 0.f);
            o.w = ev.w + fmaxf(fmaf(hn.w, sc.w, sh.w), 0.f);
            ((float4*)ehat)[i] = o;
        }
    }
}

// ---------------- launch -------------------------------------------------------
extern "C" void kernel_launch(void* const* d_in, const int* in_sizes, int n_in,
                              void* d_out, int out_size)
{
    const float* h   = (const float*)d_in[0];
    const float* e   = (const float*)d_in[1];
    const float* p   = (const float*)d_in[2];
    const int*   src = (const int*)d_in[3];
    const int*   dst = (const int*)d_in[4];
    const float* A1w = (const float*)d_in[5];
    const float* A1b = (const float*)d_in[6];
    const float* A2w = (const float*)d_in[7];
    const float* A2b = (const float*)d_in[8];
    const float* B1w = (const float*)d_in[9];
    const float* B1b = (const float*)d_in[10];
    const float* B2w = (const float*)d_in[11];
    const float* B2b = (const float*)d_in[12];
    const float* B3w = (const float*)d_in[13];
    const float* B3b = (const float*)d_in[14];
    const float* C1w = (const float*)d_in[15];
    const float* C1b = (const float*)d_in[16];
    const float* C2w = (const float*)d_in[17];
    const float* C2b = (const float*)d_in[18];
    const float* bn_h_g = (const float*)d_in[19];
    const float* bn_h_b = (const float*)d_in[20];
    const float* bn_e_g = (const float*)d_in[21];
    const float* bn_e_b = (const float*)d_in[22];

    float* out   = (float*)d_out;
    float* h_out = out;
    float* ehat  = out + (size_t)NN * D;
    float* p_out = out + (size_t)(NN + NE) * D;

    fused_gcn<<<NBLK, NTHR>>>(h, e, p, src, dst,
                              A1w, A1b, A2w, A2b,
                              B1w, B1b, B2w, B2b, B3w, B3b,
                              C1w, C1b, C2w, C2b,
                              bn_h_g, bn_h_b, bn_e_g, bn_e_b,
                              h_out, ehat, p_out);

    (void)in_sizes; (void)n_in; (void)out_size;
}

// round 7
// speedup vs baseline: 1.5762x; 1.0835x over previous
#include <cuda_runtime.h>
#include <math.h>

#define D       128
#define NN      50000
#define NE      600000
#define EPS_BN  1e-5f
#define EPS_ETA 1e-6f
#define NBLK    148
#define NTHR    1024
#define NWARP   32
#define CHUNK   338          // ceil(NN / NBLK)

// ---------------- device-global scratch (no allocations allowed) -------------
__device__ float g_b1h[NN * D];
__device__ float g_b2h[NN * D];
__device__ float g_a1h[NN * D];
__device__ float g_v[NN * D];
__device__ float g_c1p[NN * D];
__device__ float g_c2p[NN * D];
__device__ float g_agg_h[NN * D];     // h_new
__device__ float g_stats[4 * D];      // e_sum, e_sq, h_sum, h_sq
__device__ int   g_deg[NN];
__device__ int   g_start[NN];
__device__ int   g_cursor[NN];
__device__ int   g_eid[NE];
__device__ int   g_part[NBLK];
__device__ int            g_bar_count = 0;
__device__ volatile int   g_bar_gen   = 0;

__device__ __forceinline__ float sigf(float x) { return 1.0f / (1.0f + __expf(-x)); }

// ---------------- software grid barrier (all NBLK blocks co-resident) --------
__device__ __forceinline__ void grid_barrier()
{
    __syncthreads();
    if (threadIdx.x == 0) {
        int gen = g_bar_gen;
        __threadfence();
        if (atomicAdd(&g_bar_count, 1) == NBLK - 1) {
            g_bar_count = 0;
            __threadfence();
            g_bar_gen = gen + 1;
        } else {
            while (g_bar_gen == gen) { __nanosleep(64); }
        }
        __threadfence();
    }
    __syncthreads();
}

// ---------------- packed f32x2 helpers (sm_103a) -------------------------------
__device__ __forceinline__ unsigned long long pk2(float a, float b) {
    unsigned long long r;
    asm("mov.b64 %0, {%1, %2};" : "=l"(r) : "f"(a), "f"(b));
    return r;
}
__device__ __forceinline__ float2 upk2(unsigned long long v) {
    float2 r;
    asm("mov.b64 {%0, %1}, %2;" : "=f"(r.x), "=f"(r.y) : "l"(v));
    return r;
}
__device__ __forceinline__ unsigned long long ffma2(
    unsigned long long a, unsigned long long b, unsigned long long c) {
    unsigned long long d;
    asm("fma.rn.f32x2 %0, %1, %2, %3;" : "=l"(d) : "l"(a), "l"(b), "l"(c));
    return d;
}

// ---------------- FFMA2 micro-tile ----------------------------------------------
// wsh: [8][128] k-major chunk for this K-half; xs: [64][128]; 4 k-steps, 4 rows.
__device__ __forceinline__ void mm_step2(
    const float* wsh, const float* xs,
    int kk, int kbase, int r0, int c0, unsigned long long acc[4][2])
{
    float4 w0 = *(const float4*)(wsh + (kk + 0) * D + c0);
    float4 w1 = *(const float4*)(wsh + (kk + 1) * D + c0);
    float4 w2 = *(const float4*)(wsh + (kk + 2) * D + c0);
    float4 w3 = *(const float4*)(wsh + (kk + 3) * D + c0);
    unsigned long long w0a = pk2(w0.x, w0.y), w0b = pk2(w0.z, w0.w);
    unsigned long long w1a = pk2(w1.x, w1.y), w1b = pk2(w1.z, w1.w);
    unsigned long long w2a = pk2(w2.x, w2.y), w2b = pk2(w2.z, w2.w);
    unsigned long long w3a = pk2(w3.x, w3.y), w3b = pk2(w3.z, w3.w);
#pragma unroll
    for (int j = 0; j < 4; j++) {
        float4 xv = *(const float4*)(xs + (r0 + j) * D + kbase + kk);
        unsigned long long b;
        b = pk2(xv.x, xv.x);
        acc[j][0] = ffma2(b, w0a, acc[j][0]);
        acc[j][1] = ffma2(b, w0b, acc[j][1]);
        b = pk2(xv.y, xv.y);
        acc[j][0] = ffma2(b, w1a, acc[j][0]);
        acc[j][1] = ffma2(b, w1b, acc[j][1]);
        b = pk2(xv.z, xv.z);
        acc[j][0] = ffma2(b, w2a, acc[j][0]);
        acc[j][1] = ffma2(b, w2b, acc[j][1]);
        b = pk2(xv.w, xv.w);
        acc[j][0] = ffma2(b, w3a, acc[j][0]);
        acc[j][1] = ffma2(b, w3b, acc[j][1]);
    }
}

// =============================================================================
// Single fused persistent kernel. grid = 148 x 1024. K-split-2 GEMM.
// =============================================================================
__global__ void __launch_bounds__(NTHR) fused_gcn(
    const float* __restrict__ h, const float* __restrict__ e, const float* __restrict__ p,
    const int* __restrict__ src, const int* __restrict__ dst,
    const float* __restrict__ A1w, const float* __restrict__ A1b,
    const float* __restrict__ A2w, const float* __restrict__ A2b,
    const float* __restrict__ B1w, const float* __restrict__ B1b,
    const float* __restrict__ B2w, const float* __restrict__ B2b,
    const float* __restrict__ B3w, const float* __restrict__ B3b,
    const float* __restrict__ C1w, const float* __restrict__ C1b,
    const float* __restrict__ C2w, const float* __restrict__ C2b,
    const float* __restrict__ bn_h_g, const float* __restrict__ bn_h_b,
    const float* __restrict__ bn_e_g, const float* __restrict__ bn_e_b,
    float* __restrict__ h_out, float* __restrict__ ehat, float* __restrict__ p_out)
{
    __shared__ __align__(16) float xs[64 * D];   // 32 KB (X tile / scan / staging)
    __shared__ __align__(16) float ws[16 * D];   // 8 KB: 2 K-half chunks of [8][128]
    __shared__ float sA[D];
    __shared__ float sB[D];
    __shared__ int s_off;

    const int tid  = threadIdx.x;
    const int lane = tid & 31;
    const int warp = tid >> 5;
    const int bid  = blockIdx.x;
    const int c0   = lane * 4;
    const int half = warp >> 4;          // K-half: 0 or 1
    const int r0   = (warp & 15) * 4;    // 4 rows per warp within the 64-row tile
    const int kofs = half * 64;
    float* wsh = ws + half * 1024;       // this half's [8][128] chunk
    const int gtid = bid * NTHR + tid;
    const int gstr = NBLK * NTHR;

    // ---------------- Ph0: zero degree histogram + stats ----------------
    for (int i = gtid; i < NN; i += gstr) g_deg[i] = 0;
    if (gtid < 4 * D) g_stats[gtid] = 0.f;
    grid_barrier();

    // ---------------- PhA: degree histogram + node GEMMs ----------------
    for (int ei = gtid; ei < NE; ei += gstr) atomicAdd(&g_deg[dst[ei]], 1);
    {
        const int NTILE = (NN + 63) / 64;    // 782
        for (int job = bid; job < 6 * NTILE; job += NBLK) {
            int jid  = job / NTILE;
            int tile = job - jid * NTILE;
            int row0 = tile * 64;
            const float *X1 = h, *X2 = nullptr, *W = B1w, *bias = B1b;
            float* outp = g_b1h;
            int ldw = D, npass = 1;
            if      (jid == 1) { X1 = h; W = B2w; bias = B2b; outp = g_b2h; }
            else if (jid == 2) { X1 = h; W = A1w; bias = A1b; outp = g_a1h; }
            else if (jid == 3) { X1 = p; W = C1w; bias = C1b; outp = g_c1p; }
            else if (jid == 4) { X1 = p; W = C2w; bias = C2b; outp = g_c2p; }
            else if (jid == 5) { X1 = h; X2 = p; W = A2w; bias = A2b; outp = g_v; ldw = 2 * D; npass = 2; }

            unsigned long long acc[4][2];
#pragma unroll
            for (int j = 0; j < 4; j++) { acc[j][0] = 0ull; acc[j][1] = 0ull; }

            for (int pass = 0; pass < npass; pass++) {
                const float* Xc = (pass == 0) ? X1 : X2;
                const float* Wc = W + pass * D;
                __syncthreads();
                for (int i = tid; i < 64 * 32; i += NTHR) {
                    int r = i >> 5, k4 = i & 31;
                    int gr = row0 + r;
                    float4 v = make_float4(0.f, 0.f, 0.f, 0.f);
                    if (gr < NN) v = *(const float4*)(Xc + (size_t)gr * D + k4 * 4);
                    *(float4*)(xs + r * D + k4 * 4) = v;
                }
                for (int c8 = 0; c8 < 8; c8++) {
                    __syncthreads();
                    // load both halves' [8][128] W chunk, transposed
                    for (int i = tid; i < 512; i += NTHR) {
                        int hf  = i >> 8;          // 0..1
                        int rem = i & 255;
                        int c   = rem & 127;
                        int k4  = rem >> 7;        // 0..1
                        float4 w = *(const float4*)(Wc + (size_t)c * ldw + hf * 64 + c8 * 8 + k4 * 4);
                        float* wd = ws + hf * 1024;
                        wd[(k4 * 4 + 0) * D + c] = w.x;
                        wd[(k4 * 4 + 1) * D + c] = w.y;
                        wd[(k4 * 4 + 2) * D + c] = w.z;
                        wd[(k4 * 4 + 3) * D + c] = w.w;
                    }
                    __syncthreads();
                    mm_step2(wsh, xs, 0, kofs + c8 * 8, r0, c0, acc);
                    mm_step2(wsh, xs, 4, kofs + c8 * 8, r0, c0, acc);
                }
            }
            // combine K-halves via xs staging
            __syncthreads();
            if (half == 1) {
#pragma unroll
                for (int j = 0; j < 4; j++) {
                    float2 lo = upk2(acc[j][0]);
                    float2 hi = upk2(acc[j][1]);
                    *(float4*)(xs + (r0 + j) * D + c0) = make_float4(lo.x, lo.y, hi.x, hi.y);
                }
            }
            __syncthreads();
            if (half == 0) {
                float4 bb = *(const float4*)(bias + c0);
#pragma unroll
                for (int j = 0; j < 4; j++) {
                    int gr = row0 + r0 + j;
                    if (gr >= NN) continue;
                    float2 lo = upk2(acc[j][0]);
                    float2 hi = upk2(acc[j][1]);
                    float4 o = *(const float4*)(xs + (r0 + j) * D + c0);
                    float4 r = make_float4(lo.x + o.x + bb.x, lo.y + o.y + bb.y,
                                           hi.x + o.z + bb.z, hi.y + o.w + bb.w);
                    *(float4*)(outp + (size_t)gr * D + c0) = r;
                }
            }
        }
    }
    grid_barrier();

    // ---------------- PhB: local exclusive scan of degrees, then edge GEMM ----
    {
        int base = bid * CHUNK;
        int cnt  = NN - base; if (cnt > CHUNK) cnt = CHUNK; if (cnt < 0) cnt = 0;
        int* sc  = (int*)xs;
        int* sc2 = sc + 512;
        for (int i = tid; i < 512; i += NTHR) sc[i] = (i < cnt) ? g_deg[base + i] : 0;
        __syncthreads();
        int* a = sc; int* b2 = sc2;
        for (int d0 = 1; d0 < 512; d0 <<= 1) {
            for (int i = tid; i < 512; i += NTHR) {
                int v = a[i];
                if (i >= d0) v += a[i - d0];
                b2[i] = v;
            }
            __syncthreads();
            int* t = a; a = b2; b2 = t;
        }
        for (int i = tid; i < cnt; i += NTHR)
            g_start[base + i] = a[i] - g_deg[base + i];   // exclusive, unoffset
        if (tid == 0) g_part[bid] = a[511];
        __syncthreads();
    }
    // edge GEMM: hat = B3 e + b3 + b1h[src] + b2h[dst]; write ehat; e-stats.
    {
        float ps0 = 0.f, ps1 = 0.f, ps2 = 0.f, ps3 = 0.f;
        float pq0 = 0.f, pq1 = 0.f, pq2 = 0.f, pq3 = 0.f;
        const int NTILE = NE / 64;   // 9375 exact
        for (int tile = bid; tile < NTILE; tile += NBLK) {
            int row0 = tile * 64;
            unsigned long long acc[4][2];
#pragma unroll
            for (int j = 0; j < 4; j++) { acc[j][0] = 0ull; acc[j][1] = 0ull; }

            __syncthreads();
            for (int i = tid; i < 64 * 32; i += NTHR) {
                int r = i >> 5, k4 = i & 31;
                *(float4*)(xs + r * D + k4 * 4) =
                    *(const float4*)(e + (size_t)(row0 + r) * D + k4 * 4);
            }
            for (int c8 = 0; c8 < 8; c8++) {
                __syncthreads();
                for (int i = tid; i < 512; i += NTHR) {
                    int hf  = i >> 8;
                    int rem = i & 255;
                    int c   = rem & 127;
                    int k4  = rem >> 7;
                    float4 w = *(const float4*)(B3w + (size_t)c * D + hf * 64 + c8 * 8 + k4 * 4);
                    float* wd = ws + hf * 1024;
                    wd[(k4 * 4 + 0) * D + c] = w.x;
                    wd[(k4 * 4 + 1) * D + c] = w.y;
                    wd[(k4 * 4 + 2) * D + c] = w.z;
                    wd[(k4 * 4 + 3) * D + c] = w.w;
                }
                __syncthreads();
                mm_step2(wsh, xs, 0, kofs + c8 * 8, r0, c0, acc);
                mm_step2(wsh, xs, 4, kofs + c8 * 8, r0, c0, acc);
            }

            __syncthreads();
            if (half == 1) {
#pragma unroll
                for (int j = 0; j < 4; j++) {
                    float2 lo = upk2(acc[j][0]);
                    float2 hi = upk2(acc[j][1]);
                    *(float4*)(xs + (r0 + j) * D + c0) = make_float4(lo.x, lo.y, hi.x, hi.y);
                }
            }
            __syncthreads();
            if (half == 0) {
                float4 bb = *(const float4*)(B3b + c0);
#pragma unroll
                for (int j = 0; j < 4; j++) {
                    int er = row0 + r0 + j;
                    int s_ = src[er];
                    int t_ = dst[er];
                    float4 g1 = *(const float4*)(g_b1h + (size_t)s_ * D + c0);
                    float4 g2 = *(const float4*)(g_b2h + (size_t)t_ * D + c0);
                    float2 lo = upk2(acc[j][0]);
                    float2 hi = upk2(acc[j][1]);
                    float4 o = *(const float4*)(xs + (r0 + j) * D + c0);
                    float4 r;
                    r.x = lo.x + o.x + g1.x + g2.x + bb.x;
                    r.y = lo.y + o.y + g1.y + g2.y + bb.y;
                    r.z = hi.x + o.z + g1.z + g2.z + bb.z;
                    r.w = hi.y + o.w + g1.w + g2.w + bb.w;
                    *(float4*)(ehat + (size_t)er * D + c0) = r;
                    ps0 += r.x; pq0 += r.x * r.x;
                    ps1 += r.y; pq1 += r.y * r.y;
                    ps2 += r.z; pq2 += r.z * r.z;
                    ps3 += r.w; pq3 += r.w * r.w;
                }
            }
        }
        if (tid < D) { sA[tid] = 0.f; sB[tid] = 0.f; }
        __syncthreads();
        atomicAdd(&sA[c0 + 0], ps0); atomicAdd(&sB[c0 + 0], pq0);
        atomicAdd(&sA[c0 + 1], ps1); atomicAdd(&sB[c0 + 1], pq1);
        atomicAdd(&sA[c0 + 2], ps2); atomicAdd(&sB[c0 + 2], pq2);
        atomicAdd(&sA[c0 + 3], ps3); atomicAdd(&sB[c0 + 3], pq3);
        __syncthreads();
        if (tid < D) {
            atomicAdd(&g_stats[tid], sA[tid]);
            atomicAdd(&g_stats[D + tid], sB[tid]);
        }
    }
    grid_barrier();

    // ---------------- PhC: add global offsets to starts, init cursors ---------
    {
        int* sp = (int*)xs;
        for (int i = tid; i < NBLK; i += NTHR) sp[i] = g_part[i];
        __syncthreads();
        if (tid == 0) {
            int o = 0;
            for (int i = 0; i < bid; i++) o += sp[i];
            s_off = o;
        }
        __syncthreads();
        int off  = s_off;
        int base = bid * CHUNK;
        int cnt  = NN - base; if (cnt > CHUNK) cnt = CHUNK; if (cnt < 0) cnt = 0;
        for (int i = tid; i < cnt; i += NTHR) {
            int v = g_start[base + i] + off;
            g_start[base + i]  = v;
            g_cursor[base + i] = v;
        }
    }
    grid_barrier();

    // ---------------- PhD: scatter edge ids by dst ----------------
    for (int ei = gtid; ei < NE; ei += gstr) {
        int t_  = dst[ei];
        int pos = atomicAdd(&g_cursor[t_], 1);
        g_eid[pos] = ei;
    }
    grid_barrier();

    // ---------------- PhE: warp-per-node single-pass aggregation + finalize ---
    // eta = sigma/(S+eps)  =>  sum(eta*v) = sum(sigma*v) / (S+eps)
    {
        if (tid < D) { sA[tid] = 0.f; sB[tid] = 0.f; }
        __syncthreads();
        const int gw = bid * NWARP + warp;
        const int NW = NBLK * NWARP;
        float ps0 = 0.f, ps1 = 0.f, ps2 = 0.f, ps3 = 0.f;
        float pq0 = 0.f, pq1 = 0.f, pq2 = 0.f, pq3 = 0.f;

        for (int n = gw; n < NN; n += NW) {
            int st = g_start[n];
            int dg = g_deg[n];
            float4 ss = make_float4(0.f, 0.f, 0.f, 0.f);
            float4 ah = make_float4(0.f, 0.f, 0.f, 0.f);
            float4 ap = make_float4(0.f, 0.f, 0.f, 0.f);
            int i = 0;
            for (; i + 2 <= dg; i += 2) {
                int e0i = g_eid[st + i];
                int e1i = g_eid[st + i + 1];
                int sa  = src[e0i];
                int sb_ = src[e1i];
                float4 hva = *(const float4*)(ehat + (size_t)e0i * D + c0);
                float4 hvb = *(const float4*)(ehat + (size_t)e1i * D + c0);
                float4 vva = *(const float4*)(g_v + (size_t)sa * D + c0);
                float4 vvb = *(const float4*)(g_v + (size_t)sb_ * D + c0);
                float4 cpa = *(const float4*)(g_c2p + (size_t)sa * D + c0);
                float4 cpb = *(const float4*)(g_c2p + (size_t)sb_ * D + c0);
                float a0 = sigf(hva.x), a1 = sigf(hva.y), a2 = sigf(hva.z), a3 = sigf(hva.w);
                float b0 = sigf(hvb.x), b1 = sigf(hvb.y), b2 = sigf(hvb.z), b3 = sigf(hvb.w);
                ss.x += a0 + b0; ss.y += a1 + b1; ss.z += a2 + b2; ss.w += a3 + b3;
                ah.x = fmaf(a0, vva.x, fmaf(b0, vvb.x, ah.x));
                ah.y = fmaf(a1, vva.y, fmaf(b1, vvb.y, ah.y));
                ah.z = fmaf(a2, vva.z, fmaf(b2, vvb.z, ah.z));
                ah.w = fmaf(a3, vva.w, fmaf(b3, vvb.w, ah.w));
                ap.x = fmaf(a0, cpa.x, fmaf(b0, cpb.x, ap.x));
                ap.y = fmaf(a1, cpa.y, fmaf(b1, cpb.y, ap.y));
                ap.z = fmaf(a2, cpa.z, fmaf(b2, cpb.z, ap.z));
                ap.w = fmaf(a3, cpa.w, fmaf(b3, cpb.w, ap.w));
            }
            if (i < dg) {
                int eid = g_eid[st + i];
                int s_  = src[eid];
                float4 hv = *(const float4*)(ehat + (size_t)eid * D + c0);
                float4 vv = *(const float4*)(g_v + (size_t)s_ * D + c0);
                float4 cp = *(const float4*)(g_c2p + (size_t)s_ * D + c0);
                float s0 = sigf(hv.x), s1 = sigf(hv.y), s2 = sigf(hv.z), s3 = sigf(hv.w);
                ss.x += s0; ss.y += s1; ss.z += s2; ss.w += s3;
                ah.x = fmaf(s0, vv.x, ah.x);
                ah.y = fmaf(s1, vv.y, ah.y);
                ah.z = fmaf(s2, vv.z, ah.z);
                ah.w = fmaf(s3, vv.w, ah.w);
                ap.x = fmaf(s0, cp.x, ap.x);
                ap.y = fmaf(s1, cp.y, ap.y);
                ap.z = fmaf(s2, cp.z, ap.z);
                ap.w = fmaf(s3, cp.w, ap.w);
            }
            float i0 = 1.0f / (ss.x + EPS_ETA);
            float i1 = 1.0f / (ss.y + EPS_ETA);
            float i2 = 1.0f / (ss.z + EPS_ETA);
            float i3 = 1.0f / (ss.w + EPS_ETA);

            size_t off = (size_t)n * D + c0;
            float4 a1v = *(const float4*)(g_a1h + off);
            float4 hn = make_float4(fmaf(ah.x, i0, a1v.x), fmaf(ah.y, i1, a1v.y),
                                    fmaf(ah.z, i2, a1v.z), fmaf(ah.w, i3, a1v.w));
            *(float4*)(g_agg_h + off) = hn;
            ps0 += hn.x; pq0 += hn.x * hn.x;
            ps1 += hn.y; pq1 += hn.y * hn.y;
            ps2 += hn.z; pq2 += hn.z * hn.z;
            ps3 += hn.w; pq3 += hn.w * hn.w;

            float4 c1 = *(const float4*)(g_c1p + off);
            float4 pv = *(const float4*)(p + off);
            float4 po;
            po.x = pv.x + tanhf(fmaf(ap.x, i0, c1.x));
            po.y = pv.y + tanhf(fmaf(ap.y, i1, c1.y));
            po.z = pv.z + tanhf(fmaf(ap.z, i2, c1.z));
            po.w = pv.w + tanhf(fmaf(ap.w, i3, c1.w));
            *(float4*)(p_out + off) = po;
        }
        atomicAdd(&sA[c0 + 0], ps0); atomicAdd(&sB[c0 + 0], pq0);
        atomicAdd(&sA[c0 + 1], ps1); atomicAdd(&sB[c0 + 1], pq1);
        atomicAdd(&sA[c0 + 2], ps2); atomicAdd(&sB[c0 + 2], pq2);
        atomicAdd(&sA[c0 + 3], ps3); atomicAdd(&sB[c0 + 3], pq3);
        __syncthreads();
        if (tid < D) {
            atomicAdd(&g_stats[2 * D + tid], sA[tid]);
            atomicAdd(&g_stats[3 * D + tid], sB[tid]);
        }
    }
    grid_barrier();

    // ---------------- PhF: BN scale/shift + final streams ----------------
    {
        if (tid < D) {
            float me  = g_stats[tid] * (1.0f / NE);
            float ve  = g_stats[D + tid] * (1.0f / NE) - me * me;
            float sce = bn_e_g[tid] * rsqrtf(ve + EPS_BN);
            ws[tid]         = sce;
            ws[D + tid]     = bn_e_b[tid] - me * sce;
            float mh  = g_stats[2 * D + tid] * (1.0f / NN);
            float vh  = g_stats[3 * D + tid] * (1.0f / NN) - mh * mh;
            float sch = bn_h_g[tid] * rsqrtf(vh + EPS_BN);
            ws[2 * D + tid] = sch;
            ws[3 * D + tid] = bn_h_b[tid] - mh * sch;
        }
        __syncthreads();

        // h_out = h + relu(bn(h_new))
        for (int i = gtid; i < NN * 32; i += gstr) {
            int c = (i & 31) * 4;
            float4 sc = *(float4*)(ws + 2 * D + c);
            float4 sh = *(float4*)(ws + 3 * D + c);
            float4 hn = ((const float4*)g_agg_h)[i];
            float4 hv = ((const float4*)h)[i];
            float4 o;
            o.x = hv.x + fmaxf(fmaf(hn.x, sc.x, sh.x), 0.f);
            o.y = hv.y + fmaxf(fmaf(hn.y, sc.y, sh.y), 0.f);
            o.z = hv.z + fmaxf(fmaf(hn.z, sc.z, sh.z), 0.f);
            o.w = hv.w + fmaxf(fmaf(hn.w, sc.w, sh.w), 0.f);
            ((float4*)h_out)[i] = o;
        }
        // e_out = e + relu(bn(hat))  (in place over ehat)
        for (int i = gtid; i < NE * 32; i += gstr) {
            int c = (i & 31) * 4;
            float4 sc = *(float4*)(ws + c);
            float4 sh = *(float4*)(ws + D + c);
            float4 hn = ((const float4*)ehat)[i];
            float4 ev = ((const float4*)e)[i];
            float4 o;
            o.x = ev.x + fmaxf(fmaf(hn.x, sc.x, sh.x), 0.f);
            o.y = ev.y + fmaxf(fmaf(hn.y, sc.y, sh.y), 0.f);
            o.z = ev.z + fmaxf(fmaf(hn.z, sc.z, sh.z), 0.f);
            o.w = ev.w + fmaxf(fmaf(hn.w, sc.w, sh.w), 0.f);
            ((float4*)ehat)[i] = o;
        }
    }
}

// ---------------- launch -------------------------------------------------------
extern "C" void kernel_launch(void* const* d_in, const int* in_sizes, int n_in,
                              void* d_out, int out_size)
{
    const float* h   = (const float*)d_in[0];
    const float* e   = (const float*)d_in[1];
    const float* p   = (const float*)d_in[2];
    const int*   src = (const int*)d_in[3];
    const int*   dst = (const int*)d_in[4];
    const float* A1w = (const float*)d_in[5];
    const float* A1b = (const float*)d_in[6];
    const float* A2w = (const float*)d_in[7];
    const float* A2b = (const float*)d_in[8];
    const float* B1w = (const float*)d_in[9];
    const float* B1b = (const float*)d_in[10];
    const float* B2w = (const float*)d_in[11];
    const float* B2b = (const float*)d_in[12];
    const float* B3w = (const float*)d_in[13];
    const float* B3b = (const float*)d_in[14];
    const float* C1w = (const float*)d_in[15];
    const float* C1b = (const float*)d_in[16];
    const float* C2w = (const float*)d_in[17];
    const float* C2b = (const float*)d_in[18];
    const float* bn_h_g = (const float*)d_in[19];
    const float* bn_h_b = (const float*)d_in[20];
    const float* bn_e_g = (const float*)d_in[21];
    const float* bn_e_b = (const float*)d_in[22];

    float* out   = (float*)d_out;
    float* h_out = out;
    float* ehat  = out + (size_t)NN * D;
    float* p_out = out + (size_t)(NN + NE) * D;

    fused_gcn<<<NBLK, NTHR>>>(h, e, p, src, dst,
                              A1w, A1b, A2w, A2b,
                              B1w, B1b, B2w, B2b, B3w, B3b,
                              C1w, C1b, C2w, C2b,
                              bn_h_g, bn_h_b, bn_e_g, bn_e_b,
                              h_out, ehat, p_out);

    (void)in_sizes; (void)n_in; (void)out_size;
}

// round 8
// speedup vs baseline: 1.7406x; 1.1043x over previous
#include <cuda_runtime.h>
#include <math.h>

#define D       128
#define NN      50000
#define NE      600000
#define EPS_BN  1e-5f
#define EPS_ETA 1e-6f
#define NBLK    148
#define NTHR    1024
#define NWARP   32
#define CHUNK   338          // ceil(NN / NBLK)

// ---------------- device-global scratch (no allocations allowed) -------------
__device__ float g_wT[8 * D * D];     // transposed weights: [k*D + c]
                                      // 0 B1, 1 B2, 2 A1, 3 C1, 4 C2, 5 A2(h), 6 A2(p), 7 B3
__device__ float g_b1h[NN * D];
__device__ float g_b2h[NN * D];
__device__ float g_a1h[NN * D];
__device__ float g_v[NN * D];
__device__ float g_c1p[NN * D];
__device__ float g_c2p[NN * D];
__device__ float g_agg_h[NN * D];     // h_new
__device__ float g_stats[4 * D];      // e_sum, e_sq, h_sum, h_sq
__device__ int   g_deg[NN];
__device__ int   g_start[NN];
__device__ int   g_cursor[NN];
__device__ int   g_eid[NE];
__device__ int   g_part[NBLK];
__device__ int            g_bar_count = 0;
__device__ volatile int   g_bar_gen   = 0;

__device__ __forceinline__ float sigf(float x) { return 1.0f / (1.0f + __expf(-x)); }

// ---------------- software grid barrier (all NBLK blocks co-resident) --------
__device__ __forceinline__ void grid_barrier()
{
    __syncthreads();
    if (threadIdx.x == 0) {
        int gen = g_bar_gen;
        __threadfence();
        if (atomicAdd(&g_bar_count, 1) == NBLK - 1) {
            g_bar_count = 0;
            __threadfence();
            g_bar_gen = gen + 1;
        } else {
            while (g_bar_gen == gen) { __nanosleep(64); }
        }
        __threadfence();
    }
    __syncthreads();
}

// ---------------- packed f32x2 helpers (sm_103a) -------------------------------
__device__ __forceinline__ unsigned long long pk2(float a, float b) {
    unsigned long long r;
    asm("mov.b64 %0, {%1, %2};" : "=l"(r) : "f"(a), "f"(b));
    return r;
}
__device__ __forceinline__ float2 upk2(unsigned long long v) {
    float2 r;
    asm("mov.b64 {%0, %1}, %2;" : "=f"(r.x), "=f"(r.y) : "l"(v));
    return r;
}
__device__ __forceinline__ unsigned long long ffma2(
    unsigned long long a, unsigned long long b, unsigned long long c) {
    unsigned long long d;
    asm("fma.rn.f32x2 %0, %1, %2, %3;" : "=l"(d) : "l"(a), "l"(b), "l"(c));
    return d;
}

// ---------------- sync-free warp GEMM: 8 rows x 128 cols, K=128 ----------------
// Xr: base of 8 contiguous rows (stride D). wT: [k*D + c] transposed weights.
// Each lane owns cols c0..c0+3 (two f32x2 pairs). W loaded lane-spread LDG.128
// (L1-resident), X loaded warp-uniform LDG.128.
__device__ __forceinline__ void warp_gemm8(
    const float* __restrict__ Xr,
    const float* __restrict__ wT,
    int c0, unsigned long long acc[8][2])
{
    for (int k = 0; k < D; k += 4) {
        ulonglong2 w0 = *(const ulonglong2*)(wT + (size_t)(k + 0) * D + c0);
        ulonglong2 w1 = *(const ulonglong2*)(wT + (size_t)(k + 1) * D + c0);
        ulonglong2 w2 = *(const ulonglong2*)(wT + (size_t)(k + 2) * D + c0);
        ulonglong2 w3 = *(const ulonglong2*)(wT + (size_t)(k + 3) * D + c0);
#pragma unroll
        for (int j = 0; j < 8; j++) {
            float4 xv = *(const float4*)(Xr + (size_t)j * D + k);
            unsigned long long b;
            b = pk2(xv.x, xv.x);
            acc[j][0] = ffma2(b, w0.x, acc[j][0]);
            acc[j][1] = ffma2(b, w0.y, acc[j][1]);
            b = pk2(xv.y, xv.y);
            acc[j][0] = ffma2(b, w1.x, acc[j][0]);
            acc[j][1] = ffma2(b, w1.y, acc[j][1]);
            b = pk2(xv.z, xv.z);
            acc[j][0] = ffma2(b, w2.x, acc[j][0]);
            acc[j][1] = ffma2(b, w2.y, acc[j][1]);
            b = pk2(xv.w, xv.w);
            acc[j][0] = ffma2(b, w3.x, acc[j][0]);
            acc[j][1] = ffma2(b, w3.y, acc[j][1]);
        }
    }
}

// =============================================================================
// Single fused persistent kernel. grid = 148 x 1024.
// =============================================================================
__global__ void __launch_bounds__(NTHR) fused_gcn(
    const float* __restrict__ h, const float* __restrict__ e, const float* __restrict__ p,
    const int* __restrict__ src, const int* __restrict__ dst,
    const float* __restrict__ A1w, const float* __restrict__ A1b,
    const float* __restrict__ A2w, const float* __restrict__ A2b,
    const float* __restrict__ B1w, const float* __restrict__ B1b,
    const float* __restrict__ B2w, const float* __restrict__ B2b,
    const float* __restrict__ B3w, const float* __restrict__ B3b,
    const float* __restrict__ C1w, const float* __restrict__ C1b,
    const float* __restrict__ C2w, const float* __restrict__ C2b,
    const float* __restrict__ bn_h_g, const float* __restrict__ bn_h_b,
    const float* __restrict__ bn_e_g, const float* __restrict__ bn_e_b,
    float* __restrict__ h_out, float* __restrict__ ehat, float* __restrict__ p_out)
{
    __shared__ int   s_scan[512];
    __shared__ int   s_scan2[512];
    __shared__ float sA[D];
    __shared__ float sB[D];
    __shared__ float s_ss[4 * D];
    __shared__ int   s_off;

    const int tid  = threadIdx.x;
    const int lane = tid & 31;
    const int warp = tid >> 5;
    const int bid  = blockIdx.x;
    const int c0   = lane * 4;
    const int gtid = bid * NTHR + tid;
    const int gstr = NBLK * NTHR;          // 151552
    const int gw   = bid * NWARP + warp;
    const int NW   = NBLK * NWARP;         // 4736

    // ---------------- Ph0: zero deg/stats + weight transpose ----------------
    for (int i = gtid; i < NN; i += gstr) g_deg[i] = 0;
    if (gtid < 4 * D) g_stats[gtid] = 0.f;
    for (int i = gtid; i < 8 * D * D; i += gstr) {
        int j   = i >> 14;
        int rem = i & 16383;
        int k   = rem >> 7;
        int c   = rem & 127;
        float v;
        if      (j == 0) v = B1w[c * D + k];
        else if (j == 1) v = B2w[c * D + k];
        else if (j == 2) v = A1w[c * D + k];
        else if (j == 3) v = C1w[c * D + k];
        else if (j == 4) v = C2w[c * D + k];
        else if (j == 5) v = A2w[c * 2 * D + k];
        else if (j == 6) v = A2w[c * 2 * D + D + k];
        else             v = B3w[c * D + k];
        g_wT[i] = v;
    }
    grid_barrier();

    // ---------------- Ph1: dst histogram + node GEMMs (independent) ----------
    for (int ei = gtid; ei < NE; ei += gstr) atomicAdd(&g_deg[dst[ei]], 1);
    {
        const int NSTRIP = NN / 8;     // 6250 exact
        for (int job = gw; job < 6 * NSTRIP; job += NW) {
            int jid   = job / NSTRIP;
            int strip = job - jid * NSTRIP;
            int row0  = strip * 8;
            unsigned long long acc[8][2];
#pragma unroll
            for (int j = 0; j < 8; j++) { acc[j][0] = 0ull; acc[j][1] = 0ull; }

            const float* bias;
            float* outp;
            if (jid == 0) {
                warp_gemm8(h + (size_t)row0 * D, g_wT + 0 * D * D, c0, acc);
                bias = B1b; outp = g_b1h;
            } else if (jid == 1) {
                warp_gemm8(h + (size_t)row0 * D, g_wT + 1 * D * D, c0, acc);
                bias = B2b; outp = g_b2h;
            } else if (jid == 2) {
                warp_gemm8(h + (size_t)row0 * D, g_wT + 2 * D * D, c0, acc);
                bias = A1b; outp = g_a1h;
            } else if (jid == 3) {
                warp_gemm8(p + (size_t)row0 * D, g_wT + 3 * D * D, c0, acc);
                bias = C1b; outp = g_c1p;
            } else if (jid == 4) {
                warp_gemm8(p + (size_t)row0 * D, g_wT + 4 * D * D, c0, acc);
                bias = C2b; outp = g_c2p;
            } else {
                warp_gemm8(h + (size_t)row0 * D, g_wT + 5 * D * D, c0, acc);
                warp_gemm8(p + (size_t)row0 * D, g_wT + 6 * D * D, c0, acc);
                bias = A2b; outp = g_v;
            }
            float4 bb = *(const float4*)(bias + c0);
#pragma unroll
            for (int j = 0; j < 8; j++) {
                float2 lo = upk2(acc[j][0]);
                float2 hi = upk2(acc[j][1]);
                float4 r = make_float4(lo.x + bb.x, lo.y + bb.y, hi.x + bb.z, hi.y + bb.w);
                *(float4*)(outp + (size_t)(row0 + j) * D + c0) = r;
            }
        }
    }
    grid_barrier();

    // ---------------- Ph2: per-block exclusive scan of degrees ----------------
    {
        int base = bid * CHUNK;
        int cnt  = NN - base; if (cnt > CHUNK) cnt = CHUNK; if (cnt < 0) cnt = 0;
        for (int i = tid; i < 512; i += NTHR) s_scan[i] = (i < cnt) ? g_deg[base + i] : 0;
        __syncthreads();
        int* a  = s_scan;
        int* b2 = s_scan2;
        for (int d0 = 1; d0 < 512; d0 <<= 1) {
            for (int i = tid; i < 512; i += NTHR) {
                int v = a[i];
                if (i >= d0) v += a[i - d0];
                b2[i] = v;
            }
            __syncthreads();
            int* t = a; a = b2; b2 = t;
        }
        for (int i = tid; i < cnt; i += NTHR)
            g_start[base + i] = a[i] - g_deg[base + i];   // exclusive, unoffset
        if (tid == 0) g_part[bid] = a[511];
    }
    grid_barrier();

    // ---------------- Ph3: global offsets + cursors ----------------
    {
        if (tid == 0) {
            int o = 0;
            for (int i = 0; i < bid; i++) o += g_part[i];
            s_off = o;
        }
        __syncthreads();
        int off  = s_off;
        int base = bid * CHUNK;
        int cnt  = NN - base; if (cnt > CHUNK) cnt = CHUNK; if (cnt < 0) cnt = 0;
        for (int i = tid; i < cnt; i += NTHR) {
            int v = g_start[base + i] + off;
            g_start[base + i]  = v;
            g_cursor[base + i] = v;
        }
    }
    grid_barrier();

    // ---------------- Ph4: scatter by dst + edge GEMM + e-stats --------------
    {
        if (tid < D) { sA[tid] = 0.f; sB[tid] = 0.f; }
        __syncthreads();

        for (int ei = gtid; ei < NE; ei += gstr) {
            int t_  = dst[ei];
            int pos = atomicAdd(&g_cursor[t_], 1);
            g_eid[pos] = ei;
        }

        float ps0 = 0.f, ps1 = 0.f, ps2 = 0.f, ps3 = 0.f;
        float pq0 = 0.f, pq1 = 0.f, pq2 = 0.f, pq3 = 0.f;
        const float* wT = g_wT + 7 * D * D;
        float4 bb = *(const float4*)(B3b + c0);
        const int NSTRIP = NE / 8;     // 75000 exact
        for (int strip = gw; strip < NSTRIP; strip += NW) {
            int row0 = strip * 8;
            unsigned long long acc[8][2];
#pragma unroll
            for (int j = 0; j < 8; j++) { acc[j][0] = 0ull; acc[j][1] = 0ull; }
            warp_gemm8(e + (size_t)row0 * D, wT, c0, acc);
#pragma unroll
            for (int j = 0; j < 8; j++) {
                int er = row0 + j;
                int s_ = src[er];
                int t_ = dst[er];
                float4 g1 = *(const float4*)(g_b1h + (size_t)s_ * D + c0);
                float4 g2 = *(const float4*)(g_b2h + (size_t)t_ * D + c0);
                float2 lo = upk2(acc[j][0]);
                float2 hi = upk2(acc[j][1]);
                float4 r;
                r.x = lo.x + g1.x + g2.x + bb.x;
                r.y = lo.y + g1.y + g2.y + bb.y;
                r.z = hi.x + g1.z + g2.z + bb.z;
                r.w = hi.y + g1.w + g2.w + bb.w;
                *(float4*)(ehat + (size_t)er * D + c0) = r;
                ps0 += r.x; pq0 += r.x * r.x;
                ps1 += r.y; pq1 += r.y * r.y;
                ps2 += r.z; pq2 += r.z * r.z;
                ps3 += r.w; pq3 += r.w * r.w;
            }
        }
        atomicAdd(&sA[c0 + 0], ps0); atomicAdd(&sB[c0 + 0], pq0);
        atomicAdd(&sA[c0 + 1], ps1); atomicAdd(&sB[c0 + 1], pq1);
        atomicAdd(&sA[c0 + 2], ps2); atomicAdd(&sB[c0 + 2], pq2);
        atomicAdd(&sA[c0 + 3], ps3); atomicAdd(&sB[c0 + 3], pq3);
        __syncthreads();
        if (tid < D) {
            atomicAdd(&g_stats[tid], sA[tid]);
            atomicAdd(&g_stats[D + tid], sB[tid]);
        }
    }
    grid_barrier();

    // ---------------- Ph5: warp-per-node single-pass aggregation + finalize ---
    // eta = sigma/(S+eps)  =>  sum(eta*v) = sum(sigma*v) / (S+eps)
    {
        if (tid < D) { sA[tid] = 0.f; sB[tid] = 0.f; }
        __syncthreads();
        float ps0 = 0.f, ps1 = 0.f, ps2 = 0.f, ps3 = 0.f;
        float pq0 = 0.f, pq1 = 0.f, pq2 = 0.f, pq3 = 0.f;

        for (int n = gw; n < NN; n += NW) {
            int st = g_start[n];
            int dg = g_deg[n];
            float4 ss = make_float4(0.f, 0.f, 0.f, 0.f);
            float4 ah = make_float4(0.f, 0.f, 0.f, 0.f);
            float4 ap = make_float4(0.f, 0.f, 0.f, 0.f);
            int i = 0;
            for (; i + 2 <= dg; i += 2) {
                int e0i = g_eid[st + i];
                int e1i = g_eid[st + i + 1];
                int sa  = src[e0i];
                int sb_ = src[e1i];
                float4 hva = *(const float4*)(ehat + (size_t)e0i * D + c0);
                float4 hvb = *(const float4*)(ehat + (size_t)e1i * D + c0);
                float4 vva = *(const float4*)(g_v + (size_t)sa * D + c0);
                float4 vvb = *(const float4*)(g_v + (size_t)sb_ * D + c0);
                float4 cpa = *(const float4*)(g_c2p + (size_t)sa * D + c0);
                float4 cpb = *(const float4*)(g_c2p + (size_t)sb_ * D + c0);
                float a0 = sigf(hva.x), a1 = sigf(hva.y), a2 = sigf(hva.z), a3 = sigf(hva.w);
                float b0 = sigf(hvb.x), b1 = sigf(hvb.y), b2 = sigf(hvb.z), b3 = sigf(hvb.w);
                ss.x += a0 + b0; ss.y += a1 + b1; ss.z += a2 + b2; ss.w += a3 + b3;
                ah.x = fmaf(a0, vva.x, fmaf(b0, vvb.x, ah.x));
                ah.y = fmaf(a1, vva.y, fmaf(b1, vvb.y, ah.y));
                ah.z = fmaf(a2, vva.z, fmaf(b2, vvb.z, ah.z));
                ah.w = fmaf(a3, vva.w, fmaf(b3, vvb.w, ah.w));
                ap.x = fmaf(a0, cpa.x, fmaf(b0, cpb.x, ap.x));
                ap.y = fmaf(a1, cpa.y, fmaf(b1, cpb.y, ap.y));
                ap.z = fmaf(a2, cpa.z, fmaf(b2, cpb.z, ap.z));
                ap.w = fmaf(a3, cpa.w, fmaf(b3, cpb.w, ap.w));
            }
            if (i < dg) {
                int eid = g_eid[st + i];
                int s_  = src[eid];
                float4 hv = *(const float4*)(ehat + (size_t)eid * D + c0);
                float4 vv = *(const float4*)(g_v + (size_t)s_ * D + c0);
                float4 cp = *(const float4*)(g_c2p + (size_t)s_ * D + c0);
                float s0 = sigf(hv.x), s1 = sigf(hv.y), s2 = sigf(hv.z), s3 = sigf(hv.w);
                ss.x += s0; ss.y += s1; ss.z += s2; ss.w += s3;
                ah.x = fmaf(s0, vv.x, ah.x);
                ah.y = fmaf(s1, vv.y, ah.y);
                ah.z = fmaf(s2, vv.z, ah.z);
                ah.w = fmaf(s3, vv.w, ah.w);
                ap.x = fmaf(s0, cp.x, ap.x);
                ap.y = fmaf(s1, cp.y, ap.y);
                ap.z = fmaf(s2, cp.z, ap.z);
                ap.w = fmaf(s3, cp.w, ap.w);
            }
            float i0 = 1.0f / (ss.x + EPS_ETA);
            float i1 = 1.0f / (ss.y + EPS_ETA);
            float i2 = 1.0f / (ss.z + EPS_ETA);
            float i3 = 1.0f / (ss.w + EPS_ETA);

            size_t off = (size_t)n * D + c0;
            float4 a1v = *(const float4*)(g_a1h + off);
            float4 hn = make_float4(fmaf(ah.x, i0, a1v.x), fmaf(ah.y, i1, a1v.y),
                                    fmaf(ah.z, i2, a1v.z), fmaf(ah.w, i3, a1v.w));
            *(float4*)(g_agg_h + off) = hn;
            ps0 += hn.x; pq0 += hn.x * hn.x;
            ps1 += hn.y; pq1 += hn.y * hn.y;
            ps2 += hn.z; pq2 += hn.z * hn.z;
            ps3 += hn.w; pq3 += hn.w * hn.w;

            float4 c1 = *(const float4*)(g_c1p + off);
            float4 pv = *(const float4*)(p + off);
            float4 po;
            po.x = pv.x + tanhf(fmaf(ap.x, i0, c1.x));
            po.y = pv.y + tanhf(fmaf(ap.y, i1, c1.y));
            po.z = pv.z + tanhf(fmaf(ap.z, i2, c1.z));
            po.w = pv.w + tanhf(fmaf(ap.w, i3, c1.w));
            *(float4*)(p_out + off) = po;
        }
        atomicAdd(&sA[c0 + 0], ps0); atomicAdd(&sB[c0 + 0], pq0);
        atomicAdd(&sA[c0 + 1], ps1); atomicAdd(&sB[c0 + 1], pq1);
        atomicAdd(&sA[c0 + 2], ps2); atomicAdd(&sB[c0 + 2], pq2);
        atomicAdd(&sA[c0 + 3], ps3); atomicAdd(&sB[c0 + 3], pq3);
        __syncthreads();
        if (tid < D) {
            atomicAdd(&g_stats[2 * D + tid], sA[tid]);
            atomicAdd(&g_stats[3 * D + tid], sB[tid]);
        }
    }
    grid_barrier();

    // ---------------- Ph6: BN scale/shift + final streams ----------------
    {
        if (tid < D) {
            float me  = g_stats[tid] * (1.0f / NE);
            float ve  = g_stats[D + tid] * (1.0f / NE) - me * me;
            float sce = bn_e_g[tid] * rsqrtf(ve + EPS_BN);
            s_ss[tid]         = sce;
            s_ss[D + tid]     = bn_e_b[tid] - me * sce;
            float mh  = g_stats[2 * D + tid] * (1.0f / NN);
            float vh  = g_stats[3 * D + tid] * (1.0f / NN) - mh * mh;
            float sch = bn_h_g[tid] * rsqrtf(vh + EPS_BN);
            s_ss[2 * D + tid] = sch;
            s_ss[3 * D + tid] = bn_h_b[tid] - mh * sch;
        }
        __syncthreads();

        // h_out = h + relu(bn(h_new))
        for (int i = gtid; i < NN * 32; i += gstr) {
            int c = (i & 31) * 4;
            float4 sc = *(float4*)(s_ss + 2 * D + c);
            float4 sh = *(float4*)(s_ss + 3 * D + c);
            float4 hn = ((const float4*)g_agg_h)[i];
            float4 hv = ((const float4*)h)[i];
            float4 o;
            o.x = hv.x + fmaxf(fmaf(hn.x, sc.x, sh.x), 0.f);
            o.y = hv.y + fmaxf(fmaf(hn.y, sc.y, sh.y), 0.f);
            o.z = hv.z + fmaxf(fmaf(hn.z, sc.z, sh.z), 0.f);
            o.w = hv.w + fmaxf(fmaf(hn.w, sc.w, sh.w), 0.f);
            ((float4*)h_out)[i] = o;
        }
        // e_out = e + relu(bn(hat))  (in place over ehat)
        for (int i = gtid; i < NE * 32; i += gstr) {
            int c = (i & 31) * 4;
            float4 sc = *(float4*)(s_ss + c);
            float4 sh = *(float4*)(s_ss + D + c);
            float4 hn = ((const float4*)ehat)[i];
            float4 ev = ((const float4*)e)[i];
            float4 o;
            o.x = ev.x + fmaxf(fmaf(hn.x, sc.x, sh.x), 0.f);
            o.y = ev.y + fmaxf(fmaf(hn.y, sc.y, sh.y), 0.f);
            o.z = ev.z + fmaxf(fmaf(hn.z, sc.z, sh.z), 0.f);
            o.w = ev.w + fmaxf(fmaf(hn.w, sc.w, sh.w), 0.f);
            ((float4*)ehat)[i] = o;
        }
    }
}

// ---------------- launch -------------------------------------------------------
extern "C" void kernel_launch(void* const* d_in, const int* in_sizes, int n_in,
                              void* d_out, int out_size)
{
    const float* h   = (const float*)d_in[0];
    const float* e   = (const float*)d_in[1];
    const float* p   = (const float*)d_in[2];
    const int*   src = (const int*)d_in[3];
    const int*   dst = (const int*)d_in[4];
    const float* A1w = (const float*)d_in[5];
    const float* A1b = (const float*)d_in[6];
    const float* A2w = (const float*)d_in[7];
    const float* A2b = (const float*)d_in[8];
    const float* B1w = (const float*)d_in[9];
    const float* B1b = (const float*)d_in[10];
    const float* B2w = (const float*)d_in[11];
    const float* B2b = (const float*)d_in[12];
    const float* B3w = (const float*)d_in[13];
    const float* B3b = (const float*)d_in[14];
    const float* C1w = (const float*)d_in[15];
    const float* C1b = (const float*)d_in[16];
    const float* C2w = (const float*)d_in[17];
    const float* C2b = (const float*)d_in[18];
    const float* bn_h_g = (const float*)d_in[19];
    const float* bn_h_b = (const float*)d_in[20];
    const float* bn_e_g = (const float*)d_in[21];
    const float* bn_e_b = (const float*)d_in[22];

    float* out   = (float*)d_out;
    float* h_out = out;
    float* ehat  = out + (size_t)NN * D;
    float* p_out = out + (size_t)(NN + NE) * D;

    fused_gcn<<<NBLK, NTHR>>>(h, e, p, src, dst,
                              A1w, A1b, A2w, A2b,
                              B1w, B1b, B2w, B2b, B3w, B3b,
                              C1w, C1b, C2w, C2b,
                              bn_h_g, bn_h_b, bn_e_g, bn_e_b,
                              h_out, ehat, p_out);

    (void)in_sizes; (void)n_in; (void)out_size;
}

// round 9
// speedup vs baseline: 1.7631x; 1.0129x over previous
#include <cuda_runtime.h>
#include <math.h>

#define D       128
#define NN      50000
#define NE      600000
#define EPS_BN  1e-5f
#define EPS_ETA 1e-6f
#define NBLK    148
#define NTHR    1024
#define NWARP   32
#define CHUNK   338          // ceil(NN / NBLK)

// ---------------- device-global scratch (no allocations allowed) -------------
__device__ float g_wT[8 * D * D];     // transposed weights: [k*D + c]
                                      // 0 B1, 1 B2, 2 A1, 3 C1, 4 C2, 5 A2(h), 6 A2(p), 7 B3
__device__ float g_b1h[NN * D];
__device__ float g_b2h[NN * D];
__device__ float g_a1h[NN * D];
__device__ float g_v[NN * D];
__device__ float g_c1p[NN * D];
__device__ float g_c2p[NN * D];
__device__ float g_agg_h[NN * D];     // h_new
__device__ float g_stats[4 * D];      // e_sum, e_sq, h_sum, h_sq
__device__ int   g_deg[NN];
__device__ int   g_start[NN];
__device__ int   g_cursor[NN];
__device__ int   g_eid[NE];
__device__ int   g_part[NBLK];
__device__ int            g_bar_count = 0;
__device__ volatile int   g_bar_gen   = 0;

__device__ __forceinline__ float sigf(float x) { return 1.0f / (1.0f + __expf(-x)); }

// ---------------- software grid barrier (all NBLK blocks co-resident) --------
__device__ __forceinline__ void grid_barrier()
{
    __syncthreads();
    if (threadIdx.x == 0) {
        int gen = g_bar_gen;
        __threadfence();
        if (atomicAdd(&g_bar_count, 1) == NBLK - 1) {
            g_bar_count = 0;
            __threadfence();
            g_bar_gen = gen + 1;
        } else {
            while (g_bar_gen == gen) { __nanosleep(64); }
        }
        __threadfence();
    }
    __syncthreads();
}

// ---------------- packed f32x2 helpers (sm_103a) -------------------------------
__device__ __forceinline__ unsigned long long pk2(float a, float b) {
    unsigned long long r;
    asm("mov.b64 %0, {%1, %2};" : "=l"(r) : "f"(a), "f"(b));
    return r;
}
__device__ __forceinline__ float2 upk2(unsigned long long v) {
    float2 r;
    asm("mov.b64 {%0, %1}, %2;" : "=f"(r.x), "=f"(r.y) : "l"(v));
    return r;
}
__device__ __forceinline__ unsigned long long ffma2(
    unsigned long long a, unsigned long long b, unsigned long long c) {
    unsigned long long d;
    asm("fma.rn.f32x2 %0, %1, %2, %3;" : "=l"(d) : "l"(a), "l"(b), "l"(c));
    return d;
}

// ---------------- sync-free warp GEMM: 8 rows x 128 cols, K=128 ----------------
__device__ __forceinline__ void warp_gemm8(
    const float* __restrict__ Xr,
    const float* __restrict__ wT,
    int c0, unsigned long long acc[8][2])
{
    for (int k = 0; k < D; k += 4) {
        ulonglong2 w0 = *(const ulonglong2*)(wT + (size_t)(k + 0) * D + c0);
        ulonglong2 w1 = *(const ulonglong2*)(wT + (size_t)(k + 1) * D + c0);
        ulonglong2 w2 = *(const ulonglong2*)(wT + (size_t)(k + 2) * D + c0);
        ulonglong2 w3 = *(const ulonglong2*)(wT + (size_t)(k + 3) * D + c0);
#pragma unroll
        for (int j = 0; j < 8; j++) {
            float4 xv = *(const float4*)(Xr + (size_t)j * D + k);
            unsigned long long b;
            b = pk2(xv.x, xv.x);
            acc[j][0] = ffma2(b, w0.x, acc[j][0]);
            acc[j][1] = ffma2(b, w0.y, acc[j][1]);
            b = pk2(xv.y, xv.y);
            acc[j][0] = ffma2(b, w1.x, acc[j][0]);
            acc[j][1] = ffma2(b, w1.y, acc[j][1]);
            b = pk2(xv.z, xv.z);
            acc[j][0] = ffma2(b, w2.x, acc[j][0]);
            acc[j][1] = ffma2(b, w2.y, acc[j][1]);
            b = pk2(xv.w, xv.w);
            acc[j][0] = ffma2(b, w3.x, acc[j][0]);
            acc[j][1] = ffma2(b, w3.y, acc[j][1]);
        }
    }
}

// =============================================================================
// Single fused persistent kernel. grid = 148 x 1024.
// =============================================================================
__global__ void __launch_bounds__(NTHR) fused_gcn(
    const float* __restrict__ h, const float* __restrict__ e, const float* __restrict__ p,
    const int* __restrict__ src, const int* __restrict__ dst,
    const float* __restrict__ A1w, const float* __restrict__ A1b,
    const float* __restrict__ A2w, const float* __restrict__ A2b,
    const float* __restrict__ B1w, const float* __restrict__ B1b,
    const float* __restrict__ B2w, const float* __restrict__ B2b,
    const float* __restrict__ B3w, const float* __restrict__ B3b,
    const float* __restrict__ C1w, const float* __restrict__ C1b,
    const float* __restrict__ C2w, const float* __restrict__ C2b,
    const float* __restrict__ bn_h_g, const float* __restrict__ bn_h_b,
    const float* __restrict__ bn_e_g, const float* __restrict__ bn_e_b,
    float* __restrict__ h_out, float* __restrict__ ehat, float* __restrict__ p_out)
{
    __shared__ int   s_scan[512];
    __shared__ int   s_scan2[512];
    __shared__ float sA[D];
    __shared__ float sB[D];
    __shared__ float s_ss[2 * D];
    __shared__ int   s_off;

    const int tid  = threadIdx.x;
    const int lane = tid & 31;
    const int warp = tid >> 5;
    const int bid  = blockIdx.x;
    const int c0   = lane * 4;
    const int gtid = bid * NTHR + tid;
    const int gstr = NBLK * NTHR;          // 151552
    const int gw   = bid * NWARP + warp;
    const int NW   = NBLK * NWARP;         // 4736

    // ---------------- Ph0: zero deg/stats + weight transpose ----------------
    for (int i = gtid; i < NN; i += gstr) g_deg[i] = 0;
    if (gtid < 4 * D) g_stats[gtid] = 0.f;
    for (int i = gtid; i < 8 * D * D; i += gstr) {
        int j   = i >> 14;
        int rem = i & 16383;
        int k   = rem >> 7;
        int c   = rem & 127;
        float v;
        if      (j == 0) v = B1w[c * D + k];
        else if (j == 1) v = B2w[c * D + k];
        else if (j == 2) v = A1w[c * D + k];
        else if (j == 3) v = C1w[c * D + k];
        else if (j == 4) v = C2w[c * D + k];
        else if (j == 5) v = A2w[c * 2 * D + k];
        else if (j == 6) v = A2w[c * 2 * D + D + k];
        else             v = B3w[c * D + k];
        g_wT[i] = v;
    }
    grid_barrier();

    // ---------------- Ph1: dst histogram + node GEMMs (independent) ----------
    for (int ei = gtid; ei < NE; ei += gstr) atomicAdd(&g_deg[dst[ei]], 1);
    {
        const int NSTRIP = NN / 8;     // 6250 exact
        for (int job = gw; job < 6 * NSTRIP; job += NW) {
            int jid   = job / NSTRIP;
            int strip = job - jid * NSTRIP;
            int row0  = strip * 8;
            unsigned long long acc[8][2];
#pragma unroll
            for (int j = 0; j < 8; j++) { acc[j][0] = 0ull; acc[j][1] = 0ull; }

            const float* bias;
            float* outp;
            if (jid == 0) {
                warp_gemm8(h + (size_t)row0 * D, g_wT + 0 * D * D, c0, acc);
                bias = B1b; outp = g_b1h;
            } else if (jid == 1) {
                warp_gemm8(h + (size_t)row0 * D, g_wT + 1 * D * D, c0, acc);
                bias = B2b; outp = g_b2h;
            } else if (jid == 2) {
                warp_gemm8(h + (size_t)row0 * D, g_wT + 2 * D * D, c0, acc);
                bias = A1b; outp = g_a1h;
            } else if (jid == 3) {
                warp_gemm8(p + (size_t)row0 * D, g_wT + 3 * D * D, c0, acc);
                bias = C1b; outp = g_c1p;
            } else if (jid == 4) {
                warp_gemm8(p + (size_t)row0 * D, g_wT + 4 * D * D, c0, acc);
                bias = C2b; outp = g_c2p;
            } else {
                warp_gemm8(h + (size_t)row0 * D, g_wT + 5 * D * D, c0, acc);
                warp_gemm8(p + (size_t)row0 * D, g_wT + 6 * D * D, c0, acc);
                bias = A2b; outp = g_v;
            }
            float4 bb = *(const float4*)(bias + c0);
#pragma unroll
            for (int j = 0; j < 8; j++) {
                float2 lo = upk2(acc[j][0]);
                float2 hi = upk2(acc[j][1]);
                float4 r = make_float4(lo.x + bb.x, lo.y + bb.y, hi.x + bb.z, hi.y + bb.w);
                *(float4*)(outp + (size_t)(row0 + j) * D + c0) = r;
            }
        }
    }
    grid_barrier();

    // ---------------- Ph2: per-block exclusive scan of degrees ----------------
    {
        int base = bid * CHUNK;
        int cnt  = NN - base; if (cnt > CHUNK) cnt = CHUNK; if (cnt < 0) cnt = 0;
        for (int i = tid; i < 512; i += NTHR) s_scan[i] = (i < cnt) ? g_deg[base + i] : 0;
        __syncthreads();
        int* a  = s_scan;
        int* b2 = s_scan2;
        for (int d0 = 1; d0 < 512; d0 <<= 1) {
            for (int i = tid; i < 512; i += NTHR) {
                int v = a[i];
                if (i >= d0) v += a[i - d0];
                b2[i] = v;
            }
            __syncthreads();
            int* t = a; a = b2; b2 = t;
        }
        for (int i = tid; i < cnt; i += NTHR)
            g_start[base + i] = a[i] - g_deg[base + i];   // exclusive, unoffset
        if (tid == 0) g_part[bid] = a[511];
    }
    grid_barrier();

    // ---------------- Ph3: global offsets + cursors ----------------
    {
        if (tid == 0) {
            int o = 0;
            for (int i = 0; i < bid; i++) o += g_part[i];
            s_off = o;
        }
        __syncthreads();
        int off  = s_off;
        int base = bid * CHUNK;
        int cnt  = NN - base; if (cnt > CHUNK) cnt = CHUNK; if (cnt < 0) cnt = 0;
        for (int i = tid; i < cnt; i += NTHR) {
            int v = g_start[base + i] + off;
            g_start[base + i]  = v;
            g_cursor[base + i] = v;
        }
    }
    grid_barrier();

    // ---------------- Ph4: scatter by dst + edge GEMM + e-stats --------------
    {
        if (tid < D) { sA[tid] = 0.f; sB[tid] = 0.f; }
        __syncthreads();

        for (int ei = gtid; ei < NE; ei += gstr) {
            int t_  = dst[ei];
            int pos = atomicAdd(&g_cursor[t_], 1);
            g_eid[pos] = ei;
        }

        float ps0 = 0.f, ps1 = 0.f, ps2 = 0.f, ps3 = 0.f;
        float pq0 = 0.f, pq1 = 0.f, pq2 = 0.f, pq3 = 0.f;
        const float* wT = g_wT + 7 * D * D;
        float4 bb = *(const float4*)(B3b + c0);
        const int NSTRIP = NE / 8;     // 75000 exact
        for (int strip = gw; strip < NSTRIP; strip += NW) {
            int row0 = strip * 8;
            unsigned long long acc[8][2];
#pragma unroll
            for (int j = 0; j < 8; j++) { acc[j][0] = 0ull; acc[j][1] = 0ull; }
            warp_gemm8(e + (size_t)row0 * D, wT, c0, acc);
#pragma unroll
            for (int j = 0; j < 8; j++) {
                int er = row0 + j;
                int s_ = src[er];
                int t_ = dst[er];
                float4 g1 = *(const float4*)(g_b1h + (size_t)s_ * D + c0);
                float4 g2 = *(const float4*)(g_b2h + (size_t)t_ * D + c0);
                float2 lo = upk2(acc[j][0]);
                float2 hi = upk2(acc[j][1]);
                float4 r;
                r.x = lo.x + g1.x + g2.x + bb.x;
                r.y = lo.y + g1.y + g2.y + bb.y;
                r.z = hi.x + g1.z + g2.z + bb.z;
                r.w = hi.y + g1.w + g2.w + bb.w;
                *(float4*)(ehat + (size_t)er * D + c0) = r;
                ps0 += r.x; pq0 += r.x * r.x;
                ps1 += r.y; pq1 += r.y * r.y;
                ps2 += r.z; pq2 += r.z * r.z;
                ps3 += r.w; pq3 += r.w * r.w;
            }
        }
        atomicAdd(&sA[c0 + 0], ps0); atomicAdd(&sB[c0 + 0], pq0);
        atomicAdd(&sA[c0 + 1], ps1); atomicAdd(&sB[c0 + 1], pq1);
        atomicAdd(&sA[c0 + 2], ps2); atomicAdd(&sB[c0 + 2], pq2);
        atomicAdd(&sA[c0 + 3], ps3); atomicAdd(&sB[c0 + 3], pq3);
        __syncthreads();
        if (tid < D) {
            atomicAdd(&g_stats[tid], sA[tid]);
            atomicAdd(&g_stats[D + tid], sB[tid]);
        }
    }
    grid_barrier();

    // ---------------- Ph5: aggregation + fused e_final (in place) -------------
    // eta = sigma/(S+eps) => sum(eta*v) = sum(sigma*v)/(S+eps).
    // e-BN stats are complete (Ph4); each eid row is consumed by exactly one
    // warp here, so e_out = e + relu(bn(hat)) is computed and stored in place.
    {
        if (tid < D) {
            float me  = g_stats[tid] * (1.0f / NE);
            float ve  = g_stats[D + tid] * (1.0f / NE) - me * me;
            float sce = bn_e_g[tid] * rsqrtf(ve + EPS_BN);
            s_ss[tid]     = sce;
            s_ss[D + tid] = bn_e_b[tid] - me * sce;
            sA[tid] = 0.f; sB[tid] = 0.f;
        }
        __syncthreads();
        const float4 sce = *(const float4*)(s_ss + c0);
        const float4 she = *(const float4*)(s_ss + D + c0);

        float ps0 = 0.f, ps1 = 0.f, ps2 = 0.f, ps3 = 0.f;
        float pq0 = 0.f, pq1 = 0.f, pq2 = 0.f, pq3 = 0.f;

        for (int n = gw; n < NN; n += NW) {
            int st = g_start[n];
            int dg = g_deg[n];
            float4 ss = make_float4(0.f, 0.f, 0.f, 0.f);
            float4 ah = make_float4(0.f, 0.f, 0.f, 0.f);
            float4 ap = make_float4(0.f, 0.f, 0.f, 0.f);
            for (int i = 0; i < dg; i++) {
                int eid = g_eid[st + i];
                int s_  = src[eid];
                const float4 hv = *(const float4*)(ehat + (size_t)eid * D + c0);
                const float4 ev = *(const float4*)(e + (size_t)eid * D + c0);
                const float4 vv = *(const float4*)(g_v + (size_t)s_ * D + c0);
                const float4 cp = *(const float4*)(g_c2p + (size_t)s_ * D + c0);
                float s0 = sigf(hv.x), s1 = sigf(hv.y), s2 = sigf(hv.z), s3 = sigf(hv.w);
                ss.x += s0; ss.y += s1; ss.z += s2; ss.w += s3;
                ah.x = fmaf(s0, vv.x, ah.x);
                ah.y = fmaf(s1, vv.y, ah.y);
                ah.z = fmaf(s2, vv.z, ah.z);
                ah.w = fmaf(s3, vv.w, ah.w);
                ap.x = fmaf(s0, cp.x, ap.x);
                ap.y = fmaf(s1, cp.y, ap.y);
                ap.z = fmaf(s2, cp.z, ap.z);
                ap.w = fmaf(s3, cp.w, ap.w);
                float4 eo;
                eo.x = ev.x + fmaxf(fmaf(hv.x, sce.x, she.x), 0.f);
                eo.y = ev.y + fmaxf(fmaf(hv.y, sce.y, she.y), 0.f);
                eo.z = ev.z + fmaxf(fmaf(hv.z, sce.z, she.z), 0.f);
                eo.w = ev.w + fmaxf(fmaf(hv.w, sce.w, she.w), 0.f);
                *(float4*)(ehat + (size_t)eid * D + c0) = eo;
            }
            float i0 = 1.0f / (ss.x + EPS_ETA);
            float i1 = 1.0f / (ss.y + EPS_ETA);
            float i2 = 1.0f / (ss.z + EPS_ETA);
            float i3 = 1.0f / (ss.w + EPS_ETA);

            size_t off = (size_t)n * D + c0;
            float4 a1v = *(const float4*)(g_a1h + off);
            float4 hn = make_float4(fmaf(ah.x, i0, a1v.x), fmaf(ah.y, i1, a1v.y),
                                    fmaf(ah.z, i2, a1v.z), fmaf(ah.w, i3, a1v.w));
            *(float4*)(g_agg_h + off) = hn;
            ps0 += hn.x; pq0 += hn.x * hn.x;
            ps1 += hn.y; pq1 += hn.y * hn.y;
            ps2 += hn.z; pq2 += hn.z * hn.z;
            ps3 += hn.w; pq3 += hn.w * hn.w;

            float4 c1 = *(const float4*)(g_c1p + off);
            float4 pv = *(const float4*)(p + off);
            float4 po;
            po.x = pv.x + tanhf(fmaf(ap.x, i0, c1.x));
            po.y = pv.y + tanhf(fmaf(ap.y, i1, c1.y));
            po.z = pv.z + tanhf(fmaf(ap.z, i2, c1.z));
            po.w = pv.w + tanhf(fmaf(ap.w, i3, c1.w));
            *(float4*)(p_out + off) = po;
        }
        atomicAdd(&sA[c0 + 0], ps0); atomicAdd(&sB[c0 + 0], pq0);
        atomicAdd(&sA[c0 + 1], ps1); atomicAdd(&sB[c0 + 1], pq1);
        atomicAdd(&sA[c0 + 2], ps2); atomicAdd(&sB[c0 + 2], pq2);
        atomicAdd(&sA[c0 + 3], ps3); atomicAdd(&sB[c0 + 3], pq3);
        __syncthreads();
        if (tid < D) {
            atomicAdd(&g_stats[2 * D + tid], sA[tid]);
            atomicAdd(&g_stats[3 * D + tid], sB[tid]);
        }
    }
    grid_barrier();

    // ---------------- Ph6: h BN + h_out stream (75 MB) ----------------
    {
        if (tid < D) {
            float mh  = g_stats[2 * D + tid] * (1.0f / NN);
            float vh  = g_stats[3 * D + tid] * (1.0f / NN) - mh * mh;
            float sch = bn_h_g[tid] * rsqrtf(vh + EPS_BN);
            s_ss[tid]     = sch;
            s_ss[D + tid] = bn_h_b[tid] - mh * sch;
        }
        __syncthreads();

        for (int i = gtid; i < NN * 32; i += gstr) {
            int c = (i & 31) * 4;
            float4 sc = *(float4*)(s_ss + c);
            float4 sh = *(float4*)(s_ss + D + c);
            float4 hn = ((const float4*)g_agg_h)[i];
            float4 hv = ((const float4*)h)[i];
            float4 o;
            o.x = hv.x + fmaxf(fmaf(hn.x, sc.x, sh.x), 0.f);
            o.y = hv.y + fmaxf(fmaf(hn.y, sc.y, sh.y), 0.f);
            o.z = hv.z + fmaxf(fmaf(hn.z, sc.z, sh.z), 0.f);
            o.w = hv.w + fmaxf(fmaf(hn.w, sc.w, sh.w), 0.f);
            ((float4*)h_out)[i] = o;
        }
    }
}

// ---------------- launch -------------------------------------------------------
extern "C" void kernel_launch(void* const* d_in, const int* in_sizes, int n_in,
                              void* d_out, int out_size)
{
    const float* h   = (const float*)d_in[0];
    const float* e   = (const float*)d_in[1];
    const float* p   = (const float*)d_in[2];
    const int*   src = (const int*)d_in[3];
    const int*   dst = (const int*)d_in[4];
    const float* A1w = (const float*)d_in[5];
    const float* A1b = (const float*)d_in[6];
    const float* A2w = (const float*)d_in[7];
    const float* A2b = (const float*)d_in[8];
    const float* B1w = (const float*)d_in[9];
    const float* B1b = (const float*)d_in[10];
    const float* B2w = (const float*)d_in[11];
    const float* B2b = (const float*)d_in[12];
    const float* B3w = (const float*)d_in[13];
    const float* B3b = (const float*)d_in[14];
    const float* C1w = (const float*)d_in[15];
    const float* C1b = (const float*)d_in[16];
    const float* C2w = (const float*)d_in[17];
    const float* C2b = (const float*)d_in[18];
    const float* bn_h_g = (const float*)d_in[19];
    const float* bn_h_b = (const float*)d_in[20];
    const float* bn_e_g = (const float*)d_in[21];
    const float* bn_e_b = (const float*)d_in[22];

    float* out   = (float*)d_out;
    float* h_out = out;
    float* ehat  = out + (size_t)NN * D;
    float* p_out = out + (size_t)(NN + NE) * D;

    fused_gcn<<<NBLK, NTHR>>>(h, e, p, src, dst,
                              A1w, A1b, A2w, A2b,
                              B1w, B1b, B2w, B2b, B3w, B3b,
                              C1w, C1b, C2w, C2b,
                              bn_h_g, bn_h_b, bn_e_g, bn_e_b,
                              h_out, ehat, p_out);

    (void)in_sizes; (void)n_in; (void)out_size;
}